// round 10
// baseline (speedup 1.0000x reference)
#include <cuda_runtime.h>
#include <cuda_fp16.h>
#include <cstdint>
#include <math.h>

// Problem constants
#define GB 4
#define GT 1024
#define GF 1024
#define DIM 1024
#define GH 16
#define HD 64
#define MTOT (GB*GT)   // 4096

// ---------------------------------------------------------------------------
// Scratch (__device__ globals; allocation-free rule)
// ---------------------------------------------------------------------------
__device__ __half g_QH[MTOT*DIM], g_QL[MTOT*DIM];
__device__ __half g_KH[MTOT*DIM], g_KL[MTOT*DIM];
__device__ __half g_VH[MTOT*DIM], g_VL[MTOT*DIM];
__device__ __half g_AH[MTOT*DIM], g_AL[MTOT*DIM];
__device__ __half g_XtH[MTOT*DIM], g_XtL[MTOT*DIM];
__device__ __half g_XfH[MTOT*DIM], g_XfL[MTOT*DIM];
__device__ __half g_WqH[DIM*DIM],  g_WqL[DIM*DIM];
__device__ __half g_WkH[DIM*DIM],  g_WkL[DIM*DIM];
__device__ __half g_WvH[DIM*DIM],  g_WvL[DIM*DIM];
__device__ __half g_WoH[DIM*DIM],  g_WoL[DIM*DIM];
__device__ uint32_t g_mbits[MTOT*GF/32];

// ---------------------------------------------------------------------------
// Helpers
// ---------------------------------------------------------------------------
__device__ __forceinline__ uint32_t smem_u32(const void* p){
    uint32_t a;
    asm("{ .reg .u64 t; cvta.to.shared.u64 t, %1; cvt.u32.u64 %0, t; }"
        : "=r"(a) : "l"(p));
    return a;
}
__device__ __forceinline__ void ldsm4(uint32_t* r, uint32_t addr){
    asm volatile("ldmatrix.sync.aligned.m8n8.x4.shared.b16 {%0,%1,%2,%3}, [%4];"
        : "=r"(r[0]), "=r"(r[1]), "=r"(r[2]), "=r"(r[3]) : "r"(addr));
}
__device__ __forceinline__ void ldsm2(uint32_t* r, uint32_t addr){
    asm volatile("ldmatrix.sync.aligned.m8n8.x2.shared.b16 {%0,%1}, [%2];"
        : "=r"(r[0]), "=r"(r[1]) : "r"(addr));
}
__device__ __forceinline__ void ldsm4t(uint32_t* r, uint32_t addr){
    asm volatile("ldmatrix.sync.aligned.m8n8.x4.trans.shared.b16 {%0,%1,%2,%3}, [%4];"
        : "=r"(r[0]), "=r"(r[1]), "=r"(r[2]), "=r"(r[3]) : "r"(addr));
}
// f16 inputs, f32 accumulate
__device__ __forceinline__ void mma_f32(float* d, const uint32_t* a, const uint32_t* b){
    asm volatile("mma.sync.aligned.m16n8k16.row.col.f32.f16.f16.f32 "
        "{%0,%1,%2,%3}, {%4,%5,%6,%7}, {%8,%9}, {%0,%1,%2,%3};"
        : "+f"(d[0]), "+f"(d[1]), "+f"(d[2]), "+f"(d[3])
        : "r"(a[0]), "r"(a[1]), "r"(a[2]), "r"(a[3]), "r"(b[0]), "r"(b[1]));
}
// f16 inputs, f16 accumulate (2 packed regs)
__device__ __forceinline__ void mma_f16(uint32_t* d, const uint32_t* a, const uint32_t* b){
    asm volatile("mma.sync.aligned.m16n8k16.row.col.f16.f16.f16.f16 "
        "{%0,%1}, {%2,%3,%4,%5}, {%6,%7}, {%0,%1};"
        : "+r"(d[0]), "+r"(d[1])
        : "r"(a[0]), "r"(a[1]), "r"(a[2]), "r"(a[3]), "r"(b[0]), "r"(b[1]));
}
// pack two fp32 -> f16x2: low half <- lo, high half <- hi
__device__ __forceinline__ uint32_t packh(float hi, float lo){
    uint32_t r;
    asm("cvt.rn.f16x2.f32 %0, %1, %2;" : "=r"(r) : "f"(hi), "f"(lo));
    return r;
}
__device__ __forceinline__ float hlo(uint32_t r){
    return __half2float(__ushort_as_half((unsigned short)(r & 0xFFFFu)));
}
__device__ __forceinline__ float hhi(uint32_t r){
    return __half2float(__ushort_as_half((unsigned short)(r >> 16)));
}

// Branch-free exp on FMA/ALU pipes only.
__device__ __forceinline__ float fast_exp(float x){
    float xc = fmaxf(x, -87.0f);
    float r  = fmaf(xc, 1.4426950408889634f, 12582912.0f);
    int   n  = __float_as_int(r) - 0x4B400000;
    float fi = r - 12582912.0f;
    float g  = fmaf(fi, -0.6931471805599453f, xc);
    float p  = 8.3333337e-3f;
    p = fmaf(p, g, 4.1666668e-2f);
    p = fmaf(p, g, 1.6666667e-1f);
    p = fmaf(p, g, 0.5f);
    p = fmaf(p, g, 1.0f);
    p = fmaf(p, g, 1.0f);
    return p * __int_as_float((n << 23) + 0x3F800000);
}

#define CP_ASYNC16(sm, gp) \
    asm volatile("cp.async.cg.shared.global [%0], [%1], 16;" :: "r"(sm), "l"(gp))
#define CP_COMMIT() asm volatile("cp.async.commit_group;")
#define CP_WAIT1()  asm volatile("cp.async.wait_group 1;")

// ---------------------------------------------------------------------------
// Fused prep: all six fp32 -> (fp16 hi, lo) splits in one launch.
// ---------------------------------------------------------------------------
#define NX4 (MTOT*DIM/4)
#define NW4 (DIM*DIM/4)
#define NPREP (2*NX4 + 4*NW4)

__device__ __forceinline__ void split_one(
    const float4* __restrict__ x, uint2* __restrict__ h, uint2* __restrict__ l, int i)
{
    float4 v = x[i];
    union { __half b[4]; uint2 u; } H, L;
    H.b[0] = __float2half_rn(v.x);
    H.b[1] = __float2half_rn(v.y);
    H.b[2] = __float2half_rn(v.z);
    H.b[3] = __float2half_rn(v.w);
    L.b[0] = __float2half_rn(v.x - __half2float(H.b[0]));
    L.b[1] = __float2half_rn(v.y - __half2float(H.b[1]));
    L.b[2] = __float2half_rn(v.z - __half2float(H.b[2]));
    L.b[3] = __float2half_rn(v.w - __half2float(H.b[3]));
    h[i] = H.u;
    l[i] = L.u;
}

__global__ __launch_bounds__(256) void prep_split(
    const float4* __restrict__ Xt, const float4* __restrict__ Xf,
    const float4* __restrict__ Wq, const float4* __restrict__ Wk,
    const float4* __restrict__ Wv, const float4* __restrict__ Wo)
{
    int i = blockIdx.x * 256 + threadIdx.x;
    if (i < NX4) {
        split_one(Xt, (uint2*)g_XtH, (uint2*)g_XtL, i);
    } else if (i < 2*NX4) {
        split_one(Xf, (uint2*)g_XfH, (uint2*)g_XfL, i - NX4);
    } else {
        int j = i - 2*NX4;
        if (j < NW4)           split_one(Wq, (uint2*)g_WqH, (uint2*)g_WqL, j);
        else if (j < 2*NW4)    split_one(Wk, (uint2*)g_WkH, (uint2*)g_WkL, j - NW4);
        else if (j < 3*NW4)    split_one(Wv, (uint2*)g_WvH, (uint2*)g_WvL, j - 2*NW4);
        else if (j < 4*NW4)    split_one(Wo, (uint2*)g_WoH, (uint2*)g_WoL, j - 3*NW4);
    }
}

__global__ __launch_bounds__(256) void pack_mask(
    const int* __restrict__ m, uint32_t* __restrict__ bits)
{
    int i = blockIdx.x * 256 + threadIdx.x;
    unsigned v = __ballot_sync(0xffffffffu, m[i] != 0);
    if ((threadIdx.x & 31) == 0) bits[i >> 5] = v;
}

// ---------------------------------------------------------------------------
// 3-stage single-sync cp.async fp16 GEMM with f16-accum corrections.
// C = (Ah+Al)(Bh+Bl)^T + bias; main = Ah*Bh (f32 acc), corr = Ah*Bl + Al*Bh (f16 acc).
// 128x128 tile, 64B rows + XOR swizzle.
// ---------------------------------------------------------------------------
#define BM 128
#define BN 128
#define BK 32
#define TSZB 8192               // bytes per 128x32 f16 tile
#define SSTGB (4*TSZB)          // 32768 bytes per stage
#define GEMM_SMEM (3*SSTGB)     // 98304 bytes

__device__ __forceinline__ void gemm_issue(
    const __half* s0, const __half* s1,
    const __half* s2, const __half* s3,
    int kc, uint32_t sstage, int tid)
{
    const __half* src[4] = { s0, s1, s2, s3 };
#pragma unroll
    for (int t = 0; t < 4; t++) {
#pragma unroll
        for (int j = 0; j < 2; j++) {
            int idx = tid + j * 256;
            int r = idx >> 2, c = idx & 3;
            int cs = c ^ ((r >> 1) & 3);
            CP_ASYNC16(sstage + t * TSZB + r * 64 + cs * 16,
                       src[t] + (size_t)r * DIM + kc * BK + c * 8);
        }
    }
}

__global__ __launch_bounds__(256) void gemm_f16x3(
    const __half* __restrict__ Ah, const __half* __restrict__ Al,
    const __half* __restrict__ Bh, const __half* __restrict__ Bl,
    const float* __restrict__ bias, float* __restrict__ C,
    __half* __restrict__ CH, __half* __restrict__ CL)
{
    extern __shared__ __half smb[];
    const int tid = threadIdx.x, wid = tid >> 5, lane = tid & 31;
    const int bm = blockIdx.y * BM, bn = blockIdx.x * BN;
    const int wm = (wid & 1) * 64, wn = (wid >> 1) * 32;

    const __half* sA0 = Ah + (size_t)bm * DIM;
    const __half* sA1 = Al + (size_t)bm * DIM;
    const __half* sB0 = Bh + (size_t)bn * DIM;
    const __half* sB1 = Bl + (size_t)bn * DIM;

    float acc[4][4][4];
    uint32_t corr[4][4][2];
#pragma unroll
    for (int i = 0; i < 4; i++)
#pragma unroll
        for (int j = 0; j < 4; j++) {
#pragma unroll
            for (int k = 0; k < 4; k++) acc[i][j][k] = 0.0f;
            corr[i][j][0] = 0u; corr[i][j][1] = 0u;
        }

    const int seg = lane >> 3, lr = lane & 7;
    const int swz = (lr >> 1) & 3;
    const int a_rowb = (wm + (seg & 1) * 8 + lr) * 64;
    const int cA0 = (((seg >> 1)    ) ^ swz) << 4;
    const int cA1 = (((seg >> 1) + 2) ^ swz) << 4;
    const int b_rowb = (wn + lr) * 64;
    const int cB0 = (((seg & 1)     ) ^ swz) << 4;
    const int cB1 = (((seg & 1) + 2) ^ swz) << 4;

    const uint32_t sb = smem_u32(smb);

    gemm_issue(sA0, sA1, sB0, sB1, 0, sb, tid);          CP_COMMIT();
    gemm_issue(sA0, sA1, sB0, sB1, 1, sb + SSTGB, tid);  CP_COMMIT();
    CP_WAIT1();
    __syncthreads();

    for (int kc = 0; kc < DIM / BK; kc++) {
        if (kc + 2 < DIM / BK)
            gemm_issue(sA0, sA1, sB0, sB1, kc + 2,
                       sb + ((kc + 2) % 3) * SSTGB, tid);
        CP_COMMIT();

        const uint32_t st = sb + (kc % 3) * SSTGB;
#pragma unroll
        for (int ks = 0; ks < 2; ks++) {
            const int cA = ks ? cA1 : cA0;
            const int cB = ks ? cB1 : cB0;
            uint32_t bh[4][2], bl[4][2];
#pragma unroll
            for (int nt = 0; nt < 4; nt++) {
                uint32_t ad = st + 2 * TSZB + b_rowb + nt * (8 * 64) + cB;
                ldsm2(bh[nt], ad);
                ldsm2(bl[nt], ad + TSZB);
            }
#pragma unroll
            for (int mt = 0; mt < 4; mt++) {
                uint32_t ah[4], al[4];
                uint32_t ad = st + a_rowb + mt * (16 * 64) + cA;
                ldsm4(ah, ad);
                ldsm4(al, ad + TSZB);
#pragma unroll
                for (int nt = 0; nt < 4; nt++) {
                    mma_f32(acc[mt][nt],  ah, bh[nt]);   // main (f32 accum)
                    mma_f16(corr[mt][nt], ah, bl[nt]);   // corrections (f16 accum)
                    mma_f16(corr[mt][nt], al, bh[nt]);
                }
            }
        }

        CP_WAIT1();
        __syncthreads();
    }

    const int gr = lane >> 2, gc = (lane & 3) * 2;
#pragma unroll
    for (int mt = 0; mt < 4; mt++) {
#pragma unroll
        for (int nt = 0; nt < 4; nt++) {
            int col  = bn + wn + nt * 8 + gc;
            float b0 = bias[col], b1 = bias[col + 1];
            size_t r0 = (size_t)(bm + wm + mt * 16 + gr) * DIM + col;
            size_t r1 = r0 + 8 * DIM;
            float v0 = acc[mt][nt][0] + hlo(corr[mt][nt][0]) + b0;
            float v1 = acc[mt][nt][1] + hhi(corr[mt][nt][0]) + b1;
            float v2 = acc[mt][nt][2] + hlo(corr[mt][nt][1]) + b0;
            float v3 = acc[mt][nt][3] + hhi(corr[mt][nt][1]) + b1;
            if (CH) {
                uint32_t h0 = packh(v1, v0);
                uint32_t l0 = packh(v1 - hhi(h0), v0 - hlo(h0));
                uint32_t h1 = packh(v3, v2);
                uint32_t l1 = packh(v3 - hhi(h1), v2 - hlo(h1));
                *(uint32_t*)&CH[r0] = h0; *(uint32_t*)&CL[r0] = l0;
                *(uint32_t*)&CH[r1] = h1; *(uint32_t*)&CL[r1] = l1;
            } else {
                float2 w0 = { v0, v1 }, w1 = { v2, v3 };
                *(float2*)&C[r0] = w0;
                *(float2*)&C[r1] = w1;
            }
        }
    }
}

// ---------------------------------------------------------------------------
// Tensor-core flash attention (fp16, f16-accum corrections), FT=64,
// 3-stage single-sync KV pipeline.
// ---------------------------------------------------------------------------
#define ALD 72
#define SQH 0
#define SQL 9216
#define SKV0 18432
#define KVARR 4608
#define KVSTG (4*KVARR)
#define ATT_SMEM ((SKV0 + 3*KVSTG)*2)   // 147456 bytes

__device__ __forceinline__ void kv_issue(
    const __half* KH, const __half* KL,
    const __half* VH, const __half* VL,
    size_t gfrow, int hof, uint32_t stbase, int tid)
{
#pragma unroll
    for (int j = 0; j < 2; j++) {
        int idx = tid + j * 256;
        int r = idx >> 3, c = (idx & 7) * 8;
        size_t g = (gfrow + r) * DIM + hof + c;
        uint32_t so = stbase + (r * ALD + c) * 2;
        CP_ASYNC16(so,                KH + g);
        CP_ASYNC16(so + KVARR * 2,    KL + g);
        CP_ASYNC16(so + 2*KVARR * 2,  VH + g);
        CP_ASYNC16(so + 3*KVARR * 2,  VL + g);
    }
}

__global__ __launch_bounds__(256, 1) void attn_mma(
    const __half* __restrict__ QH, const __half* __restrict__ QL,
    const __half* __restrict__ KH, const __half* __restrict__ KL,
    const __half* __restrict__ VH, const __half* __restrict__ VL,
    const uint32_t* __restrict__ mbits,
    __half* __restrict__ AHo, __half* __restrict__ ALo)
{
    extern __shared__ __half sm[];
    const int tid = threadIdx.x, w = tid >> 5, lane = tid & 31;
    const int t0 = blockIdx.x * 128, h = blockIdx.y, b = blockIdx.z;
    const int lr = lane & 7, seg = lane >> 3;
    const int gr = lane >> 2, qc = (lane & 3) * 2;
    const uint32_t sb = smem_u32(sm);
    const int hof = h * HD;
    const size_t gfbase = (size_t)(b * GF);

    kv_issue(KH, KL, VH, VL, gfbase,      hof, sb + SKV0 * 2, tid);           CP_COMMIT();
    kv_issue(KH, KL, VH, VL, gfbase + 64, hof, sb + (SKV0 + KVSTG) * 2, tid); CP_COMMIT();

    // Load Q tile (hi/lo)
    {
        const size_t grow = (size_t)(b * GT + t0);
#pragma unroll
        for (int j = 0; j < 4; j++) {
            int idx = tid + j * 256;
            int r = idx >> 3, c = (idx & 7) * 8;
            size_t g = (grow + r) * DIM + hof + c;
            *(uint4*)&sm[SQH + r * ALD + c] = *(const uint4*)&QH[g];
            *(uint4*)&sm[SQL + r * ALD + c] = *(const uint4*)&QL[g];
        }
    }
    CP_WAIT1();
    __syncthreads();

    uint32_t qh[4][4], ql[4][4];
#pragma unroll
    for (int kc = 0; kc < 4; kc++) {
        uint32_t ad = sb + ((w * 16 + (seg & 1) * 8 + lr) * ALD + kc * 16 + (seg >> 1) * 8) * 2;
        ldsm4(qh[kc], ad + SQH * 2);
        ldsm4(ql[kc], ad + SQL * 2);
    }

    float oacc[8][4];
#pragma unroll
    for (int i = 0; i < 8; i++)
#pragma unroll
        for (int j = 0; j < 4; j++) oacc[i][j] = 0.0f;
    float m0 = -1e30f, m1 = -1e30f, l0 = 0.0f, l1 = 0.0f;

    const int mrow0 = b * GT + t0 + w * 16 + gr;
    const uint32_t* mrp0 = mbits + (size_t)mrow0 * (GF / 32);
    const uint32_t* mrp1 = mrp0 + 8 * (GF / 32);

    for (int ftile = 0; ftile < 16; ftile++) {
        if (ftile + 2 < 16)
            kv_issue(KH, KL, VH, VL, gfbase + (ftile + 2) * 64, hof,
                     sb + (SKV0 + ((ftile + 2) % 3) * KVSTG) * 2, tid);
        CP_COMMIT();

        const uint32_t stg = SKV0 + (ftile % 3) * KVSTG;

        uint2 mw0 = *(const uint2*)(mrp0 + ftile * 2);
        uint2 mw1 = *(const uint2*)(mrp1 + ftile * 2);
        uint32_t wA[2] = { mw0.x, mw0.y };
        uint32_t wB[2] = { mw1.x, mw1.y };

        // S = Q K^T : main f32, corrections f16
        float sacc[8][4];
        uint32_t scorr[8][2];
#pragma unroll
        for (int nt = 0; nt < 8; nt++) {
#pragma unroll
            for (int j = 0; j < 4; j++) sacc[nt][j] = 0.0f;
            scorr[nt][0] = 0u; scorr[nt][1] = 0u;
        }
#pragma unroll
        for (int nt = 0; nt < 8; nt++) {
            uint32_t bh[8], bl[8];
#pragma unroll
            for (int kcg = 0; kcg < 2; kcg++) {
                uint32_t ad = sb + (stg + (nt * 8 + lr) * ALD + kcg * 32 + seg * 8) * 2;
                ldsm4(&bh[kcg * 4], ad);
                ldsm4(&bl[kcg * 4], ad + KVARR * 2);
            }
#pragma unroll
            for (int kc = 0; kc < 4; kc++) {
                mma_f32(sacc[nt],  qh[kc], &bh[kc * 2]);
                mma_f16(scorr[nt], qh[kc], &bl[kc * 2]);
                mma_f16(scorr[nt], ql[kc], &bh[kc * 2]);
            }
            sacc[nt][0] += hlo(scorr[nt][0]);
            sacc[nt][1] += hhi(scorr[nt][0]);
            sacc[nt][2] += hlo(scorr[nt][1]);
            sacc[nt][3] += hhi(scorr[nt][1]);
        }

        // mask + scale + row max
        float rm0 = -1e30f, rm1 = -1e30f;
#pragma unroll
        for (int nt = 0; nt < 8; nt++) {
            uint32_t sh = (nt & 3) * 8 + qc;
            uint32_t bA = wA[nt >> 2] >> sh;
            uint32_t bB = wB[nt >> 2] >> sh;
            float s0 = (bA & 1u) ? sacc[nt][0] * 0.125f : -10000.0f;
            float s1 = (bA & 2u) ? sacc[nt][1] * 0.125f : -10000.0f;
            float s2 = (bB & 1u) ? sacc[nt][2] * 0.125f : -10000.0f;
            float s3 = (bB & 2u) ? sacc[nt][3] * 0.125f : -10000.0f;
            sacc[nt][0] = s0; sacc[nt][1] = s1; sacc[nt][2] = s2; sacc[nt][3] = s3;
            rm0 = fmaxf(rm0, fmaxf(s0, s1));
            rm1 = fmaxf(rm1, fmaxf(s2, s3));
        }
        rm0 = fmaxf(rm0, __shfl_xor_sync(0xffffffffu, rm0, 1));
        rm0 = fmaxf(rm0, __shfl_xor_sync(0xffffffffu, rm0, 2));
        rm1 = fmaxf(rm1, __shfl_xor_sync(0xffffffffu, rm1, 1));
        rm1 = fmaxf(rm1, __shfl_xor_sync(0xffffffffu, rm1, 2));
        float mn0 = fmaxf(m0, rm0), mn1 = fmaxf(m1, rm1);
        float c0 = fast_exp(m0 - mn0), c1 = fast_exp(m1 - mn1);
        m0 = mn0; m1 = mn1;

        // P = exp(s-m), pack hi/lo fp16, row sums
        uint32_t pah[4][4], pal[4][4];
        float rs0 = 0.0f, rs1 = 0.0f;
#pragma unroll
        for (int kc = 0; kc < 4; kc++) {
            float p0 = fast_exp(sacc[2*kc][0] - m0);
            float p1 = fast_exp(sacc[2*kc][1] - m0);
            float p2 = fast_exp(sacc[2*kc][2] - m1);
            float p3 = fast_exp(sacc[2*kc][3] - m1);
            float p4 = fast_exp(sacc[2*kc+1][0] - m0);
            float p5 = fast_exp(sacc[2*kc+1][1] - m0);
            float p6 = fast_exp(sacc[2*kc+1][2] - m1);
            float p7 = fast_exp(sacc[2*kc+1][3] - m1);
            rs0 += (p0 + p1) + (p4 + p5);
            rs1 += (p2 + p3) + (p6 + p7);
            uint32_t h0 = packh(p1, p0), h1 = packh(p3, p2);
            uint32_t h2 = packh(p5, p4), h3 = packh(p7, p6);
            pah[kc][0] = h0; pah[kc][1] = h1; pah[kc][2] = h2; pah[kc][3] = h3;
            pal[kc][0] = packh(p1 - hhi(h0), p0 - hlo(h0));
            pal[kc][1] = packh(p3 - hhi(h1), p2 - hlo(h1));
            pal[kc][2] = packh(p5 - hhi(h2), p4 - hlo(h2));
            pal[kc][3] = packh(p7 - hhi(h3), p6 - hlo(h3));
        }
        rs0 += __shfl_xor_sync(0xffffffffu, rs0, 1);
        rs0 += __shfl_xor_sync(0xffffffffu, rs0, 2);
        rs1 += __shfl_xor_sync(0xffffffffu, rs1, 1);
        rs1 += __shfl_xor_sync(0xffffffffu, rs1, 2);
        l0 = l0 * c0 + rs0;
        l1 = l1 * c1 + rs1;

#pragma unroll
        for (int nt = 0; nt < 8; nt++) {
            oacc[nt][0] *= c0; oacc[nt][1] *= c0;
            oacc[nt][2] *= c1; oacc[nt][3] *= c1;
        }

        // O += P V : main f32, corrections f16 (folded per ftile)
        uint32_t ocorr[8][2];
#pragma unroll
        for (int nt = 0; nt < 8; nt++) { ocorr[nt][0] = 0u; ocorr[nt][1] = 0u; }
#pragma unroll
        for (int kcg = 0; kcg < 2; kcg++) {
#pragma unroll
            for (int nt = 0; nt < 8; nt++) {
                uint32_t bvh[4], bvl[4];
                uint32_t ad = sb + (stg + 2*KVARR + (kcg * 32 + seg * 8 + lr) * ALD + nt * 8) * 2;
                ldsm4t(bvh, ad);
                ldsm4t(bvl, ad + KVARR * 2);
                mma_f32(oacc[nt],  pah[2*kcg],   bvh);
                mma_f16(ocorr[nt], pal[2*kcg],   bvh);
                mma_f16(ocorr[nt], pah[2*kcg],   bvl);
                mma_f32(oacc[nt],  pah[2*kcg+1], &bvh[2]);
                mma_f16(ocorr[nt], pal[2*kcg+1], &bvh[2]);
                mma_f16(ocorr[nt], pah[2*kcg+1], &bvl[2]);
            }
        }
#pragma unroll
        for (int nt = 0; nt < 8; nt++) {
            oacc[nt][0] += hlo(ocorr[nt][0]);
            oacc[nt][1] += hhi(ocorr[nt][0]);
            oacc[nt][2] += hlo(ocorr[nt][1]);
            oacc[nt][3] += hhi(ocorr[nt][1]);
        }

        CP_WAIT1();
        __syncthreads();
    }

    // Epilogue
    float inv0 = 1.0f / l0, inv1 = 1.0f / l1;
    size_t orow = (size_t)(b * GT + t0 + w * 16 + gr) * DIM + hof;
#pragma unroll
    for (int nt = 0; nt < 8; nt++) {
        int col = nt * 8 + qc;
        float v0 = oacc[nt][0] * inv0, v1 = oacc[nt][1] * inv0;
        float v2 = oacc[nt][2] * inv1, v3 = oacc[nt][3] * inv1;
        uint32_t h0 = packh(v1, v0);
        uint32_t l0p = packh(v1 - hhi(h0), v0 - hlo(h0));
        uint32_t h1 = packh(v3, v2);
        uint32_t l1p = packh(v3 - hhi(h1), v2 - hlo(h1));
        *(uint32_t*)&AHo[orow + col] = h0;
        *(uint32_t*)&ALo[orow + col] = l0p;
        *(uint32_t*)&AHo[orow + 8 * DIM + col] = h1;
        *(uint32_t*)&ALo[orow + 8 * DIM + col] = l1p;
    }
}

// ---------------------------------------------------------------------------
// Launch
// ---------------------------------------------------------------------------
extern "C" void kernel_launch(void* const* d_in, const int* in_sizes, int n_in,
                              void* d_out, int out_size)
{
    const float* X_to   = (const float*)d_in[0];
    const float* X_from = (const float*)d_in[1];
    const int*   maskp  = (const int*)  d_in[2];
    const float* Wq = (const float*)d_in[3];
    const float* bq = (const float*)d_in[4];
    const float* Wk = (const float*)d_in[5];
    const float* bk = (const float*)d_in[6];
    const float* Wv = (const float*)d_in[7];
    const float* bv = (const float*)d_in[8];
    const float* Wo = (const float*)d_in[9];
    const float* bo = (const float*)d_in[10];
    float* out = (float*)d_out;

    __half *QH,*QL,*KH,*KL,*VH,*VL,*AH,*AL;
    __half *XtH,*XtL,*XfH,*XfL;
    __half *WqH,*WqL,*WkH,*WkL,*WvH,*WvL,*WoH,*WoL;
    uint32_t* mbits;
    cudaGetSymbolAddress((void**)&QH, g_QH); cudaGetSymbolAddress((void**)&QL, g_QL);
    cudaGetSymbolAddress((void**)&KH, g_KH); cudaGetSymbolAddress((void**)&KL, g_KL);
    cudaGetSymbolAddress((void**)&VH, g_VH); cudaGetSymbolAddress((void**)&VL, g_VL);
    cudaGetSymbolAddress((void**)&AH, g_AH); cudaGetSymbolAddress((void**)&AL, g_AL);
    cudaGetSymbolAddress((void**)&XtH, g_XtH); cudaGetSymbolAddress((void**)&XtL, g_XtL);
    cudaGetSymbolAddress((void**)&XfH, g_XfH); cudaGetSymbolAddress((void**)&XfL, g_XfL);
    cudaGetSymbolAddress((void**)&WqH, g_WqH); cudaGetSymbolAddress((void**)&WqL, g_WqL);
    cudaGetSymbolAddress((void**)&WkH, g_WkH); cudaGetSymbolAddress((void**)&WkL, g_WkL);
    cudaGetSymbolAddress((void**)&WvH, g_WvH); cudaGetSymbolAddress((void**)&WvL, g_WvL);
    cudaGetSymbolAddress((void**)&WoH, g_WoH); cudaGetSymbolAddress((void**)&WoL, g_WoL);
    cudaGetSymbolAddress((void**)&mbits, g_mbits);

    cudaFuncSetAttribute(gemm_f16x3,
                         cudaFuncAttributeMaxDynamicSharedMemorySize, GEMM_SMEM);
    cudaFuncSetAttribute(attn_mma,
                         cudaFuncAttributeMaxDynamicSharedMemorySize, ATT_SMEM);

    prep_split<<<NPREP / 256, 256>>>((const float4*)X_to, (const float4*)X_from,
                                     (const float4*)Wq, (const float4*)Wk,
                                     (const float4*)Wv, (const float4*)Wo);
    pack_mask<<<(MTOT * GF) / 256, 256>>>(maskp, mbits);

    dim3 gg(DIM / BN, MTOT / BM);   // (8, 32)

    // Projections -> fp16 hi/lo pairs. NOTE reference's swap: K<=Wv/bv, V<=Wk/bk.
    gemm_f16x3<<<gg, 256, GEMM_SMEM>>>(XtH, XtL, WqH, WqL, bq, nullptr, QH, QL);
    gemm_f16x3<<<gg, 256, GEMM_SMEM>>>(XfH, XfL, WvH, WvL, bv, nullptr, KH, KL);
    gemm_f16x3<<<gg, 256, GEMM_SMEM>>>(XfH, XfL, WkH, WkL, bk, nullptr, VH, VL);

    dim3 ag(GT / 128, GH, GB);      // (8, 16, 4)
    attn_mma<<<ag, 256, ATT_SMEM>>>(QH, QL, KH, KL, VH, VL, mbits, AH, AL);

    // Output projection (fp32 out)
    gemm_f16x3<<<gg, 256, GEMM_SMEM>>>(AH, AL, WoH, WoL, bo, out, nullptr, nullptr);
}

// round 11
// speedup vs baseline: 1.3766x; 1.3766x over previous
#include <cuda_runtime.h>
#include <cuda_bf16.h>
#include <cuda_fp16.h>
#include <cstdint>
#include <math.h>

// Problem constants
#define GB 4
#define GT 1024
#define GF 1024
#define DIM 1024
#define GH 16
#define HD 64
#define MTOT (GB*GT)   // 4096

// ---------------------------------------------------------------------------
// Scratch (__device__ globals; allocation-free rule)
// ---------------------------------------------------------------------------
// score path (bf16)
__device__ __nv_bfloat16 g_QH[MTOT*DIM], g_QL[MTOT*DIM];
__device__ __nv_bfloat16 g_KH[MTOT*DIM], g_KL[MTOT*DIM];
__device__ __nv_bfloat16 g_XtH[MTOT*DIM], g_XtL[MTOT*DIM];
__device__ __nv_bfloat16 g_XfH[MTOT*DIM], g_XfL[MTOT*DIM];
__device__ __nv_bfloat16 g_WqH[DIM*DIM],  g_WqL[DIM*DIM];
__device__ __nv_bfloat16 g_WvH[DIM*DIM],  g_WvL[DIM*DIM];
// value path (fp16)
__device__ __half g_Xf16[MTOT*DIM];
__device__ __half g_VH[MTOT*DIM];
__device__ __half g_AH[MTOT*DIM];
__device__ __half g_WkH[DIM*DIM], g_WkL[DIM*DIM];
__device__ __half g_WoH[DIM*DIM], g_WoL[DIM*DIM];
__device__ uint32_t g_mbits[MTOT*GF/32];

// ---------------------------------------------------------------------------
// Helpers
// ---------------------------------------------------------------------------
__device__ __forceinline__ uint32_t smem_u32(const void* p){
    uint32_t a;
    asm("{ .reg .u64 t; cvta.to.shared.u64 t, %1; cvt.u32.u64 %0, t; }"
        : "=r"(a) : "l"(p));
    return a;
}
__device__ __forceinline__ void ldsm4(uint32_t* r, uint32_t addr){
    asm volatile("ldmatrix.sync.aligned.m8n8.x4.shared.b16 {%0,%1,%2,%3}, [%4];"
        : "=r"(r[0]), "=r"(r[1]), "=r"(r[2]), "=r"(r[3]) : "r"(addr));
}
__device__ __forceinline__ void ldsm2(uint32_t* r, uint32_t addr){
    asm volatile("ldmatrix.sync.aligned.m8n8.x2.shared.b16 {%0,%1}, [%2];"
        : "=r"(r[0]), "=r"(r[1]) : "r"(addr));
}
__device__ __forceinline__ void ldsm4t(uint32_t* r, uint32_t addr){
    asm volatile("ldmatrix.sync.aligned.m8n8.x4.trans.shared.b16 {%0,%1,%2,%3}, [%4];"
        : "=r"(r[0]), "=r"(r[1]), "=r"(r[2]), "=r"(r[3]) : "r"(addr));
}
__device__ __forceinline__ void mma_bf16(float* d, const uint32_t* a, const uint32_t* b){
    asm volatile("mma.sync.aligned.m16n8k16.row.col.f32.bf16.bf16.f32 "
        "{%0,%1,%2,%3}, {%4,%5,%6,%7}, {%8,%9}, {%0,%1,%2,%3};"
        : "+f"(d[0]), "+f"(d[1]), "+f"(d[2]), "+f"(d[3])
        : "r"(a[0]), "r"(a[1]), "r"(a[2]), "r"(a[3]), "r"(b[0]), "r"(b[1]));
}
__device__ __forceinline__ void mma_h16(float* d, const uint32_t* a, const uint32_t* b){
    asm volatile("mma.sync.aligned.m16n8k16.row.col.f32.f16.f16.f32 "
        "{%0,%1,%2,%3}, {%4,%5,%6,%7}, {%8,%9}, {%0,%1,%2,%3};"
        : "+f"(d[0]), "+f"(d[1]), "+f"(d[2]), "+f"(d[3])
        : "r"(a[0]), "r"(a[1]), "r"(a[2]), "r"(a[3]), "r"(b[0]), "r"(b[1]));
}
__device__ __forceinline__ uint32_t packbf(float hi, float lo){
    uint32_t r;
    asm("cvt.rn.bf16x2.f32 %0, %1, %2;" : "=r"(r) : "f"(hi), "f"(lo));
    return r;
}
__device__ __forceinline__ float bflo(uint32_t r){ return __int_as_float(r << 16); }
__device__ __forceinline__ float bfhi(uint32_t r){ return __int_as_float(r & 0xFFFF0000u); }
__device__ __forceinline__ uint32_t packh(float hi, float lo){
    uint32_t r;
    asm("cvt.rn.f16x2.f32 %0, %1, %2;" : "=r"(r) : "f"(hi), "f"(lo));
    return r;
}

// Branch-free exp on FMA/ALU pipes only.
__device__ __forceinline__ float fast_exp(float x){
    float xc = fmaxf(x, -87.0f);
    float r  = fmaf(xc, 1.4426950408889634f, 12582912.0f);
    int   n  = __float_as_int(r) - 0x4B400000;
    float fi = r - 12582912.0f;
    float g  = fmaf(fi, -0.6931471805599453f, xc);
    float p  = 8.3333337e-3f;
    p = fmaf(p, g, 4.1666668e-2f);
    p = fmaf(p, g, 1.6666667e-1f);
    p = fmaf(p, g, 0.5f);
    p = fmaf(p, g, 1.0f);
    p = fmaf(p, g, 1.0f);
    return p * __int_as_float((n << 23) + 0x3F800000);
}

#define CP_ASYNC16(sm, gp) \
    asm volatile("cp.async.cg.shared.global [%0], [%1], 16;" :: "r"(sm), "l"(gp))
#define CP_COMMIT() asm volatile("cp.async.commit_group;")
#define CP_WAIT1()  asm volatile("cp.async.wait_group 1;")

// ---------------------------------------------------------------------------
// Fused prep
// ---------------------------------------------------------------------------
#define NX4 (MTOT*DIM/4)
#define NW4 (DIM*DIM/4)
#define NPREP (2*NX4 + 4*NW4)

__device__ __forceinline__ void split_bf(
    const float4* __restrict__ x, uint2* __restrict__ h, uint2* __restrict__ l, int i)
{
    float4 v = x[i];
    union { __nv_bfloat16 b[4]; uint2 u; } H, L;
    H.b[0] = __float2bfloat16(v.x);
    H.b[1] = __float2bfloat16(v.y);
    H.b[2] = __float2bfloat16(v.z);
    H.b[3] = __float2bfloat16(v.w);
    L.b[0] = __float2bfloat16(v.x - __bfloat162float(H.b[0]));
    L.b[1] = __float2bfloat16(v.y - __bfloat162float(H.b[1]));
    L.b[2] = __float2bfloat16(v.z - __bfloat162float(H.b[2]));
    L.b[3] = __float2bfloat16(v.w - __bfloat162float(H.b[3]));
    h[i] = H.u;
    l[i] = L.u;
}
__device__ __forceinline__ void split_h(
    const float4* __restrict__ x, uint2* __restrict__ h, uint2* __restrict__ l, int i)
{
    float4 v = x[i];
    union { __half b[4]; uint2 u; } H, L;
    H.b[0] = __float2half_rn(v.x);
    H.b[1] = __float2half_rn(v.y);
    H.b[2] = __float2half_rn(v.z);
    H.b[3] = __float2half_rn(v.w);
    L.b[0] = __float2half_rn(v.x - __half2float(H.b[0]));
    L.b[1] = __float2half_rn(v.y - __half2float(H.b[1]));
    L.b[2] = __float2half_rn(v.z - __half2float(H.b[2]));
    L.b[3] = __float2half_rn(v.w - __half2float(H.b[3]));
    h[i] = H.u;
    l[i] = L.u;
}

__global__ __launch_bounds__(256) void prep_split(
    const float4* __restrict__ Xt, const float4* __restrict__ Xf,
    const float4* __restrict__ Wq, const float4* __restrict__ Wk,
    const float4* __restrict__ Wv, const float4* __restrict__ Wo)
{
    int i = blockIdx.x * 256 + threadIdx.x;
    if (i < NX4) {
        split_bf(Xt, (uint2*)g_XtH, (uint2*)g_XtL, i);
    } else if (i < 2*NX4) {
        int j = i - NX4;
        split_bf(Xf, (uint2*)g_XfH, (uint2*)g_XfL, j);
        // fp16 single copy for V projection
        float4 v = Xf[j];
        union { __half b[4]; uint2 u; } H;
        H.b[0] = __float2half_rn(v.x);
        H.b[1] = __float2half_rn(v.y);
        H.b[2] = __float2half_rn(v.z);
        H.b[3] = __float2half_rn(v.w);
        ((uint2*)g_Xf16)[j] = H.u;
    } else {
        int j = i - 2*NX4;
        if (j < NW4)           split_bf(Wq, (uint2*)g_WqH, (uint2*)g_WqL, j);
        else if (j < 2*NW4)    split_bf(Wv, (uint2*)g_WvH, (uint2*)g_WvL, j - NW4);
        else if (j < 3*NW4)    split_h (Wk, (uint2*)g_WkH, (uint2*)g_WkL, j - 2*NW4);
        else if (j < 4*NW4)    split_h (Wo, (uint2*)g_WoH, (uint2*)g_WoL, j - 3*NW4);
    }
}

__global__ __launch_bounds__(256) void pack_mask(
    const int* __restrict__ m, uint32_t* __restrict__ bits)
{
    int i = blockIdx.x * 256 + threadIdx.x;
    unsigned v = __ballot_sync(0xffffffffu, m[i] != 0);
    if ((threadIdx.x & 31) == 0) bits[i >> 5] = v;
}

// ---------------------------------------------------------------------------
// 3-stage single-sync cp.async mma.sync bf16x3 GEMM (R8-exact, best measured).
// ---------------------------------------------------------------------------
#define BM 128
#define BN 128
#define BK 32
#define TSZB 8192
#define SSTGB (4*TSZB)
#define GEMM_SMEM (3*SSTGB)

__device__ __forceinline__ void gemm_issue(
    const __nv_bfloat16* s0, const __nv_bfloat16* s1,
    const __nv_bfloat16* s2, const __nv_bfloat16* s3,
    int kc, uint32_t sstage, int tid)
{
    const __nv_bfloat16* src[4] = { s0, s1, s2, s3 };
#pragma unroll
    for (int t = 0; t < 4; t++) {
#pragma unroll
        for (int j = 0; j < 2; j++) {
            int idx = tid + j * 256;
            int r = idx >> 2, c = idx & 3;
            int cs = c ^ ((r >> 1) & 3);
            CP_ASYNC16(sstage + t * TSZB + r * 64 + cs * 16,
                       src[t] + (size_t)r * DIM + kc * BK + c * 8);
        }
    }
}

__global__ __launch_bounds__(256, 2) void gemm_bf16x3(
    const __nv_bfloat16* __restrict__ Ah, const __nv_bfloat16* __restrict__ Al,
    const __nv_bfloat16* __restrict__ Bh, const __nv_bfloat16* __restrict__ Bl,
    const float* __restrict__ bias,
    __nv_bfloat16* __restrict__ CH, __nv_bfloat16* __restrict__ CL)
{
    extern __shared__ __nv_bfloat16 smb[];
    const int tid = threadIdx.x, wid = tid >> 5, lane = tid & 31;
    const int bm = blockIdx.y * BM, bn = blockIdx.x * BN;
    const int wm = (wid & 1) * 64, wn = (wid >> 1) * 32;

    const __nv_bfloat16* sA0 = Ah + (size_t)bm * DIM;
    const __nv_bfloat16* sA1 = Al + (size_t)bm * DIM;
    const __nv_bfloat16* sB0 = Bh + (size_t)bn * DIM;
    const __nv_bfloat16* sB1 = Bl + (size_t)bn * DIM;

    float acc[4][4][4];
#pragma unroll
    for (int i = 0; i < 4; i++)
#pragma unroll
        for (int j = 0; j < 4; j++)
#pragma unroll
            for (int k = 0; k < 4; k++) acc[i][j][k] = 0.0f;

    const int seg = lane >> 3, lr = lane & 7;
    const int swz = (lr >> 1) & 3;
    const int a_rowb = (wm + (seg & 1) * 8 + lr) * 64;
    const int cA0 = (((seg >> 1)    ) ^ swz) << 4;
    const int cA1 = (((seg >> 1) + 2) ^ swz) << 4;
    const int b_rowb = (wn + lr) * 64;
    const int cB0 = (((seg & 1)     ) ^ swz) << 4;
    const int cB1 = (((seg & 1) + 2) ^ swz) << 4;

    const uint32_t sb = smem_u32(smb);

    gemm_issue(sA0, sA1, sB0, sB1, 0, sb, tid);          CP_COMMIT();
    gemm_issue(sA0, sA1, sB0, sB1, 1, sb + SSTGB, tid);  CP_COMMIT();
    CP_WAIT1();
    __syncthreads();

    for (int kc = 0; kc < DIM / BK; kc++) {
        if (kc + 2 < DIM / BK)
            gemm_issue(sA0, sA1, sB0, sB1, kc + 2,
                       sb + ((kc + 2) % 3) * SSTGB, tid);
        CP_COMMIT();

        const uint32_t st = sb + (kc % 3) * SSTGB;
#pragma unroll
        for (int ks = 0; ks < 2; ks++) {
            const int cA = ks ? cA1 : cA0;
            const int cB = ks ? cB1 : cB0;
            uint32_t bh[4][2], bl[4][2];
#pragma unroll
            for (int nt = 0; nt < 4; nt++) {
                uint32_t ad = st + 2 * TSZB + b_rowb + nt * (8 * 64) + cB;
                ldsm2(bh[nt], ad);
                ldsm2(bl[nt], ad + TSZB);
            }
#pragma unroll
            for (int mt = 0; mt < 4; mt++) {
                uint32_t ah[4], al[4];
                uint32_t ad = st + a_rowb + mt * (16 * 64) + cA;
                ldsm4(ah, ad);
                ldsm4(al, ad + TSZB);
#pragma unroll
                for (int nt = 0; nt < 4; nt++) {
                    mma_bf16(acc[mt][nt], ah, bh[nt]);
                    mma_bf16(acc[mt][nt], ah, bl[nt]);
                    mma_bf16(acc[mt][nt], al, bh[nt]);
                }
            }
        }

        CP_WAIT1();
        __syncthreads();
    }

    const int gr = lane >> 2, gc = (lane & 3) * 2;
#pragma unroll
    for (int mt = 0; mt < 4; mt++) {
#pragma unroll
        for (int nt = 0; nt < 4; nt++) {
            int col  = bn + wn + nt * 8 + gc;
            float b0 = bias[col], b1 = bias[col + 1];
            size_t r0 = (size_t)(bm + wm + mt * 16 + gr) * DIM + col;
            size_t r1 = r0 + 8 * DIM;
            float v0 = acc[mt][nt][0] + b0, v1 = acc[mt][nt][1] + b1;
            float v2 = acc[mt][nt][2] + b0, v3 = acc[mt][nt][3] + b1;
            uint32_t h0 = packbf(v1, v0);
            uint32_t l0 = packbf(v1 - bfhi(h0), v0 - bflo(h0));
            uint32_t h1 = packbf(v3, v2);
            uint32_t l1 = packbf(v3 - bfhi(h1), v2 - bflo(h1));
            *(uint32_t*)&CH[r0] = h0; *(uint32_t*)&CL[r0] = l0;
            *(uint32_t*)&CH[r1] = h1; *(uint32_t*)&CL[r1] = l1;
        }
    }
}

// ---------------------------------------------------------------------------
// fp16 2-term GEMM: C = A·(Bh+Bl)^T + bias. A single fp16, B hi/lo fp16.
// 2 mma per k16. Output: fp16 single (CH) or fp32 (C).
// ---------------------------------------------------------------------------
#define VSSTGB (3*TSZB)          // 24576 bytes per stage (A, Bh, Bl)
#define VGEMM_SMEM (3*VSSTGB)    // 73728 bytes

__device__ __forceinline__ void vgemm_issue(
    const __half* sA, const __half* sBh, const __half* sBl,
    int kc, uint32_t sstage, int tid)
{
    const __half* src[3] = { sA, sBh, sBl };
#pragma unroll
    for (int t = 0; t < 3; t++) {
#pragma unroll
        for (int j = 0; j < 2; j++) {
            int idx = tid + j * 256;
            int r = idx >> 2, c = idx & 3;
            int cs = c ^ ((r >> 1) & 3);
            CP_ASYNC16(sstage + t * TSZB + r * 64 + cs * 16,
                       src[t] + (size_t)r * DIM + kc * BK + c * 8);
        }
    }
}

__global__ __launch_bounds__(256, 2) void gemm_f16_2t(
    const __half* __restrict__ A,
    const __half* __restrict__ Bh, const __half* __restrict__ Bl,
    const float* __restrict__ bias, float* __restrict__ C,
    __half* __restrict__ CH)
{
    extern __shared__ __half smh[];
    const int tid = threadIdx.x, wid = tid >> 5, lane = tid & 31;
    const int bm = blockIdx.y * BM, bn = blockIdx.x * BN;
    const int wm = (wid & 1) * 64, wn = (wid >> 1) * 32;

    const __half* sA  = A  + (size_t)bm * DIM;
    const __half* sB0 = Bh + (size_t)bn * DIM;
    const __half* sB1 = Bl + (size_t)bn * DIM;

    float acc[4][4][4];
#pragma unroll
    for (int i = 0; i < 4; i++)
#pragma unroll
        for (int j = 0; j < 4; j++)
#pragma unroll
            for (int k = 0; k < 4; k++) acc[i][j][k] = 0.0f;

    const int seg = lane >> 3, lr = lane & 7;
    const int swz = (lr >> 1) & 3;
    const int a_rowb = (wm + (seg & 1) * 8 + lr) * 64;
    const int cA0 = (((seg >> 1)    ) ^ swz) << 4;
    const int cA1 = (((seg >> 1) + 2) ^ swz) << 4;
    const int b_rowb = (wn + lr) * 64;
    const int cB0 = (((seg & 1)     ) ^ swz) << 4;
    const int cB1 = (((seg & 1) + 2) ^ swz) << 4;

    const uint32_t sb = smem_u32(smh);

    vgemm_issue(sA, sB0, sB1, 0, sb, tid);           CP_COMMIT();
    vgemm_issue(sA, sB0, sB1, 1, sb + VSSTGB, tid);  CP_COMMIT();
    CP_WAIT1();
    __syncthreads();

    for (int kc = 0; kc < DIM / BK; kc++) {
        if (kc + 2 < DIM / BK)
            vgemm_issue(sA, sB0, sB1, kc + 2,
                        sb + ((kc + 2) % 3) * VSSTGB, tid);
        CP_COMMIT();

        const uint32_t st = sb + (kc % 3) * VSSTGB;
#pragma unroll
        for (int ks = 0; ks < 2; ks++) {
            const int cA = ks ? cA1 : cA0;
            const int cB = ks ? cB1 : cB0;
            uint32_t bh[4][2], bl[4][2];
#pragma unroll
            for (int nt = 0; nt < 4; nt++) {
                uint32_t ad = st + TSZB + b_rowb + nt * (8 * 64) + cB;
                ldsm2(bh[nt], ad);
                ldsm2(bl[nt], ad + TSZB);
            }
#pragma unroll
            for (int mt = 0; mt < 4; mt++) {
                uint32_t ah[4];
                ldsm4(ah, st + a_rowb + mt * (16 * 64) + cA);
#pragma unroll
                for (int nt = 0; nt < 4; nt++) {
                    mma_h16(acc[mt][nt], ah, bh[nt]);
                    mma_h16(acc[mt][nt], ah, bl[nt]);
                }
            }
        }

        CP_WAIT1();
        __syncthreads();
    }

    const int gr = lane >> 2, gc = (lane & 3) * 2;
#pragma unroll
    for (int mt = 0; mt < 4; mt++) {
#pragma unroll
        for (int nt = 0; nt < 4; nt++) {
            int col  = bn + wn + nt * 8 + gc;
            float b0 = bias[col], b1 = bias[col + 1];
            size_t r0 = (size_t)(bm + wm + mt * 16 + gr) * DIM + col;
            size_t r1 = r0 + 8 * DIM;
            float v0 = acc[mt][nt][0] + b0, v1 = acc[mt][nt][1] + b1;
            float v2 = acc[mt][nt][2] + b0, v3 = acc[mt][nt][3] + b1;
            if (CH) {
                *(uint32_t*)&CH[r0] = packh(v1, v0);
                *(uint32_t*)&CH[r1] = packh(v3, v2);
            } else {
                float2 w0 = { v0, v1 }, w1 = { v2, v3 };
                *(float2*)&C[r0] = w0;
                *(float2*)&C[r1] = w1;
            }
        }
    }
}

// ---------------------------------------------------------------------------
// Tensor-core flash attention: QK^T bf16x3, P·V fp16 single-term.
// FT=64, 3-stage single-sync KV pipeline. KV stage = {KH,KL bf16, VH fp16}.
// ---------------------------------------------------------------------------
#define ALD 72
#define SQH 0
#define SQL 9216
#define SKV0 18432
#define KVARR 4608
#define KVSTG (3*KVARR)
#define ATT_SMEM ((SKV0 + 3*KVSTG)*2)   // 119808 bytes

__device__ __forceinline__ void kv_issue(
    const __nv_bfloat16* KH, const __nv_bfloat16* KL, const __half* VH,
    size_t gfrow, int hof, uint32_t stbase, int tid)
{
#pragma unroll
    for (int j = 0; j < 2; j++) {
        int idx = tid + j * 256;
        int r = idx >> 3, c = (idx & 7) * 8;
        size_t g = (gfrow + r) * DIM + hof + c;
        uint32_t so = stbase + (r * ALD + c) * 2;
        CP_ASYNC16(so,                KH + g);
        CP_ASYNC16(so + KVARR * 2,    KL + g);
        CP_ASYNC16(so + 2*KVARR * 2,  VH + g);
    }
}

__global__ __launch_bounds__(256, 1) void attn_mma(
    const __nv_bfloat16* __restrict__ QH, const __nv_bfloat16* __restrict__ QL,
    const __nv_bfloat16* __restrict__ KH, const __nv_bfloat16* __restrict__ KL,
    const __half* __restrict__ VH,
    const uint32_t* __restrict__ mbits,
    __half* __restrict__ AHo)
{
    extern __shared__ __nv_bfloat16 sm[];
    const int tid = threadIdx.x, w = tid >> 5, lane = tid & 31;
    const int t0 = blockIdx.x * 128, h = blockIdx.y, b = blockIdx.z;
    const int lr = lane & 7, seg = lane >> 3;
    const int gr = lane >> 2, qc = (lane & 3) * 2;
    const uint32_t sb = smem_u32(sm);
    const int hof = h * HD;
    const size_t gfbase = (size_t)(b * GF);

    kv_issue(KH, KL, VH, gfbase,      hof, sb + SKV0 * 2, tid);           CP_COMMIT();
    kv_issue(KH, KL, VH, gfbase + 64, hof, sb + (SKV0 + KVSTG) * 2, tid); CP_COMMIT();

    // Load Q tile (hi/lo)
    {
        const size_t grow = (size_t)(b * GT + t0);
#pragma unroll
        for (int j = 0; j < 4; j++) {
            int idx = tid + j * 256;
            int r = idx >> 3, c = (idx & 7) * 8;
            size_t g = (grow + r) * DIM + hof + c;
            *(uint4*)&sm[SQH + r * ALD + c] = *(const uint4*)&QH[g];
            *(uint4*)&sm[SQL + r * ALD + c] = *(const uint4*)&QL[g];
        }
    }
    CP_WAIT1();
    __syncthreads();

    uint32_t qh[4][4], ql[4][4];
#pragma unroll
    for (int kc = 0; kc < 4; kc++) {
        uint32_t ad = sb + ((w * 16 + (seg & 1) * 8 + lr) * ALD + kc * 16 + (seg >> 1) * 8) * 2;
        ldsm4(qh[kc], ad + SQH * 2);
        ldsm4(ql[kc], ad + SQL * 2);
    }

    float oacc[8][4];
#pragma unroll
    for (int i = 0; i < 8; i++)
#pragma unroll
        for (int j = 0; j < 4; j++) oacc[i][j] = 0.0f;
    float m0 = -1e30f, m1 = -1e30f, l0 = 0.0f, l1 = 0.0f;

    const int mrow0 = b * GT + t0 + w * 16 + gr;
    const uint32_t* mrp0 = mbits + (size_t)mrow0 * (GF / 32);
    const uint32_t* mrp1 = mrp0 + 8 * (GF / 32);

    for (int ftile = 0; ftile < 16; ftile++) {
        if (ftile + 2 < 16)
            kv_issue(KH, KL, VH, gfbase + (ftile + 2) * 64, hof,
                     sb + (SKV0 + ((ftile + 2) % 3) * KVSTG) * 2, tid);
        CP_COMMIT();

        const uint32_t stg = SKV0 + (ftile % 3) * KVSTG;

        uint2 mw0 = *(const uint2*)(mrp0 + ftile * 2);
        uint2 mw1 = *(const uint2*)(mrp1 + ftile * 2);
        uint32_t wA[2] = { mw0.x, mw0.y };
        uint32_t wB[2] = { mw1.x, mw1.y };

        // S = Q K^T (bf16x3)
        float sacc[8][4];
#pragma unroll
        for (int nt = 0; nt < 8; nt++) {
#pragma unroll
            for (int j = 0; j < 4; j++) sacc[nt][j] = 0.0f;
        }
#pragma unroll
        for (int nt = 0; nt < 8; nt++) {
            uint32_t bh[8], bl[8];
#pragma unroll
            for (int kcg = 0; kcg < 2; kcg++) {
                uint32_t ad = sb + (stg + (nt * 8 + lr) * ALD + kcg * 32 + seg * 8) * 2;
                ldsm4(&bh[kcg * 4], ad);
                ldsm4(&bl[kcg * 4], ad + KVARR * 2);
            }
#pragma unroll
            for (int kc = 0; kc < 4; kc++) {
                mma_bf16(sacc[nt], qh[kc], &bh[kc * 2]);
                mma_bf16(sacc[nt], qh[kc], &bl[kc * 2]);
                mma_bf16(sacc[nt], ql[kc], &bh[kc * 2]);
            }
        }

        // mask + scale + row max
        float rm0 = -1e30f, rm1 = -1e30f;
#pragma unroll
        for (int nt = 0; nt < 8; nt++) {
            uint32_t sh = (nt & 3) * 8 + qc;
            uint32_t bA = wA[nt >> 2] >> sh;
            uint32_t bB = wB[nt >> 2] >> sh;
            float s0 = (bA & 1u) ? sacc[nt][0] * 0.125f : -10000.0f;
            float s1 = (bA & 2u) ? sacc[nt][1] * 0.125f : -10000.0f;
            float s2 = (bB & 1u) ? sacc[nt][2] * 0.125f : -10000.0f;
            float s3 = (bB & 2u) ? sacc[nt][3] * 0.125f : -10000.0f;
            sacc[nt][0] = s0; sacc[nt][1] = s1; sacc[nt][2] = s2; sacc[nt][3] = s3;
            rm0 = fmaxf(rm0, fmaxf(s0, s1));
            rm1 = fmaxf(rm1, fmaxf(s2, s3));
        }
        rm0 = fmaxf(rm0, __shfl_xor_sync(0xffffffffu, rm0, 1));
        rm0 = fmaxf(rm0, __shfl_xor_sync(0xffffffffu, rm0, 2));
        rm1 = fmaxf(rm1, __shfl_xor_sync(0xffffffffu, rm1, 1));
        rm1 = fmaxf(rm1, __shfl_xor_sync(0xffffffffu, rm1, 2));
        float mn0 = fmaxf(m0, rm0), mn1 = fmaxf(m1, rm1);
        float c0 = fast_exp(m0 - mn0), c1 = fast_exp(m1 - mn1);
        m0 = mn0; m1 = mn1;

        // P = exp(s-m), pack fp16 hi only, row sums
        uint32_t pah[4][4];
        float rs0 = 0.0f, rs1 = 0.0f;
#pragma unroll
        for (int kc = 0; kc < 4; kc++) {
            float p0 = fast_exp(sacc[2*kc][0] - m0);
            float p1 = fast_exp(sacc[2*kc][1] - m0);
            float p2 = fast_exp(sacc[2*kc][2] - m1);
            float p3 = fast_exp(sacc[2*kc][3] - m1);
            float p4 = fast_exp(sacc[2*kc+1][0] - m0);
            float p5 = fast_exp(sacc[2*kc+1][1] - m0);
            float p6 = fast_exp(sacc[2*kc+1][2] - m1);
            float p7 = fast_exp(sacc[2*kc+1][3] - m1);
            rs0 += (p0 + p1) + (p4 + p5);
            rs1 += (p2 + p3) + (p6 + p7);
            pah[kc][0] = packh(p1, p0);
            pah[kc][1] = packh(p3, p2);
            pah[kc][2] = packh(p5, p4);
            pah[kc][3] = packh(p7, p6);
        }
        rs0 += __shfl_xor_sync(0xffffffffu, rs0, 1);
        rs0 += __shfl_xor_sync(0xffffffffu, rs0, 2);
        rs1 += __shfl_xor_sync(0xffffffffu, rs1, 1);
        rs1 += __shfl_xor_sync(0xffffffffu, rs1, 2);
        l0 = l0 * c0 + rs0;
        l1 = l1 * c1 + rs1;

#pragma unroll
        for (int nt = 0; nt < 8; nt++) {
            oacc[nt][0] *= c0; oacc[nt][1] *= c0;
            oacc[nt][2] *= c1; oacc[nt][3] *= c1;
        }

        // O += P V (fp16 single-term)
#pragma unroll
        for (int kcg = 0; kcg < 2; kcg++) {
#pragma unroll
            for (int nt = 0; nt < 8; nt++) {
                uint32_t bvh[4];
                uint32_t ad = sb + (stg + 2*KVARR + (kcg * 32 + seg * 8 + lr) * ALD + nt * 8) * 2;
                ldsm4t(bvh, ad);
                mma_h16(oacc[nt], pah[2*kcg],   &bvh[0]);
                mma_h16(oacc[nt], pah[2*kcg+1], &bvh[2]);
            }
        }

        CP_WAIT1();
        __syncthreads();
    }

    // Epilogue: fp16 single output
    float inv0 = 1.0f / l0, inv1 = 1.0f / l1;
    size_t orow = (size_t)(b * GT + t0 + w * 16 + gr) * DIM + hof;
#pragma unroll
    for (int nt = 0; nt < 8; nt++) {
        int col = nt * 8 + qc;
        float v0 = oacc[nt][0] * inv0, v1 = oacc[nt][1] * inv0;
        float v2 = oacc[nt][2] * inv1, v3 = oacc[nt][3] * inv1;
        *(uint32_t*)&AHo[orow + col] = packh(v1, v0);
        *(uint32_t*)&AHo[orow + 8 * DIM + col] = packh(v3, v2);
    }
}

// ---------------------------------------------------------------------------
// Launch
// ---------------------------------------------------------------------------
extern "C" void kernel_launch(void* const* d_in, const int* in_sizes, int n_in,
                              void* d_out, int out_size)
{
    const float* X_to   = (const float*)d_in[0];
    const float* X_from = (const float*)d_in[1];
    const int*   maskp  = (const int*)  d_in[2];
    const float* Wq = (const float*)d_in[3];
    const float* bq = (const float*)d_in[4];
    const float* Wk = (const float*)d_in[5];
    const float* bk = (const float*)d_in[6];
    const float* Wv = (const float*)d_in[7];
    const float* bv = (const float*)d_in[8];
    const float* Wo = (const float*)d_in[9];
    const float* bo = (const float*)d_in[10];
    float* out = (float*)d_out;

    __nv_bfloat16 *QH,*QL,*KH,*KL,*XtH,*XtL,*XfH,*XfL,*WqH,*WqL,*WvH,*WvL;
    __half *Xf16,*VH,*AH,*WkH,*WkL,*WoH,*WoL;
    uint32_t* mbits;
    cudaGetSymbolAddress((void**)&QH, g_QH); cudaGetSymbolAddress((void**)&QL, g_QL);
    cudaGetSymbolAddress((void**)&KH, g_KH); cudaGetSymbolAddress((void**)&KL, g_KL);
    cudaGetSymbolAddress((void**)&XtH, g_XtH); cudaGetSymbolAddress((void**)&XtL, g_XtL);
    cudaGetSymbolAddress((void**)&XfH, g_XfH); cudaGetSymbolAddress((void**)&XfL, g_XfL);
    cudaGetSymbolAddress((void**)&WqH, g_WqH); cudaGetSymbolAddress((void**)&WqL, g_WqL);
    cudaGetSymbolAddress((void**)&WvH, g_WvH); cudaGetSymbolAddress((void**)&WvL, g_WvL);
    cudaGetSymbolAddress((void**)&Xf16, g_Xf16);
    cudaGetSymbolAddress((void**)&VH, g_VH);
    cudaGetSymbolAddress((void**)&AH, g_AH);
    cudaGetSymbolAddress((void**)&WkH, g_WkH); cudaGetSymbolAddress((void**)&WkL, g_WkL);
    cudaGetSymbolAddress((void**)&WoH, g_WoH); cudaGetSymbolAddress((void**)&WoL, g_WoL);
    cudaGetSymbolAddress((void**)&mbits, g_mbits);

    cudaFuncSetAttribute(gemm_bf16x3,
                         cudaFuncAttributeMaxDynamicSharedMemorySize, GEMM_SMEM);
    cudaFuncSetAttribute(gemm_f16_2t,
                         cudaFuncAttributeMaxDynamicSharedMemorySize, VGEMM_SMEM);
    cudaFuncSetAttribute(attn_mma,
                         cudaFuncAttributeMaxDynamicSharedMemorySize, ATT_SMEM);

    prep_split<<<NPREP / 256, 256>>>((const float4*)X_to, (const float4*)X_from,
                                     (const float4*)Wq, (const float4*)Wk,
                                     (const float4*)Wv, (const float4*)Wo);
    pack_mask<<<(MTOT * GF) / 256, 256>>>(maskp, mbits);

    dim3 gg(DIM / BN, MTOT / BM);   // (8, 32)

    // Score path (bf16x3). NOTE reference's swap: K <= Wv/bv.
    gemm_bf16x3<<<gg, 256, GEMM_SMEM>>>(XtH, XtL, WqH, WqL, bq, QH, QL);
    gemm_bf16x3<<<gg, 256, GEMM_SMEM>>>(XfH, XfL, WvH, WvL, bv, KH, KL);
    // Value path (fp16 2-term). V <= Wk/bk per reference swap.
    gemm_f16_2t<<<gg, 256, VGEMM_SMEM>>>(Xf16, WkH, WkL, bk, nullptr, VH);

    dim3 ag(GT / 128, GH, GB);      // (8, 16, 4)
    attn_mma<<<ag, 256, ATT_SMEM>>>(QH, QL, KH, KL, VH, mbits, AH);

    // Output projection (fp16 2-term, fp32 out)
    gemm_f16_2t<<<gg, 256, VGEMM_SMEM>>>(AH, WoH, WoL, bo, out, nullptr);
}

// round 12
// speedup vs baseline: 1.7913x; 1.3013x over previous
#include <cuda_runtime.h>
#include <cuda_fp16.h>
#include <cstdint>
#include <math.h>

// Problem constants
#define GB 4
#define GT 1024
#define GF 1024
#define DIM 1024
#define GH 16
#define HD 64
#define MTOT (GB*GT)   // 4096

// ---------------------------------------------------------------------------
// Scratch (__device__ globals; allocation-free rule)
// ---------------------------------------------------------------------------
__device__ __half g_Q[MTOT*DIM];
__device__ __half g_K[MTOT*DIM];
__device__ __half g_V[MTOT*DIM];
__device__ __half g_A[MTOT*DIM];
__device__ __half g_Xt16[MTOT*DIM];
__device__ __half g_Xf16[MTOT*DIM];
__device__ __half g_WqH[DIM*DIM], g_WqL[DIM*DIM];
__device__ __half g_WkH[DIM*DIM], g_WkL[DIM*DIM];
__device__ __half g_WvH[DIM*DIM], g_WvL[DIM*DIM];
__device__ __half g_WoH[DIM*DIM], g_WoL[DIM*DIM];
__device__ uint32_t g_mbits[MTOT*GF/32];

// ---------------------------------------------------------------------------
// Helpers
// ---------------------------------------------------------------------------
__device__ __forceinline__ uint32_t smem_u32(const void* p){
    uint32_t a;
    asm("{ .reg .u64 t; cvta.to.shared.u64 t, %1; cvt.u32.u64 %0, t; }"
        : "=r"(a) : "l"(p));
    return a;
}
__device__ __forceinline__ void ldsm4(uint32_t* r, uint32_t addr){
    asm volatile("ldmatrix.sync.aligned.m8n8.x4.shared.b16 {%0,%1,%2,%3}, [%4];"
        : "=r"(r[0]), "=r"(r[1]), "=r"(r[2]), "=r"(r[3]) : "r"(addr));
}
__device__ __forceinline__ void ldsm2(uint32_t* r, uint32_t addr){
    asm volatile("ldmatrix.sync.aligned.m8n8.x2.shared.b16 {%0,%1}, [%2];"
        : "=r"(r[0]), "=r"(r[1]) : "r"(addr));
}
__device__ __forceinline__ void ldsm4t(uint32_t* r, uint32_t addr){
    asm volatile("ldmatrix.sync.aligned.m8n8.x4.trans.shared.b16 {%0,%1,%2,%3}, [%4];"
        : "=r"(r[0]), "=r"(r[1]), "=r"(r[2]), "=r"(r[3]) : "r"(addr));
}
__device__ __forceinline__ void mma_h16(float* d, const uint32_t* a, const uint32_t* b){
    asm volatile("mma.sync.aligned.m16n8k16.row.col.f32.f16.f16.f32 "
        "{%0,%1,%2,%3}, {%4,%5,%6,%7}, {%8,%9}, {%0,%1,%2,%3};"
        : "+f"(d[0]), "+f"(d[1]), "+f"(d[2]), "+f"(d[3])
        : "r"(a[0]), "r"(a[1]), "r"(a[2]), "r"(a[3]), "r"(b[0]), "r"(b[1]));
}
__device__ __forceinline__ uint32_t packh(float hi, float lo){
    uint32_t r;
    asm("cvt.rn.f16x2.f32 %0, %1, %2;" : "=r"(r) : "f"(hi), "f"(lo));
    return r;
}

// Branch-free exp on FMA/ALU pipes only.
__device__ __forceinline__ float fast_exp(float x){
    float xc = fmaxf(x, -87.0f);
    float r  = fmaf(xc, 1.4426950408889634f, 12582912.0f);
    int   n  = __float_as_int(r) - 0x4B400000;
    float fi = r - 12582912.0f;
    float g  = fmaf(fi, -0.6931471805599453f, xc);
    float p  = 8.3333337e-3f;
    p = fmaf(p, g, 4.1666668e-2f);
    p = fmaf(p, g, 1.6666667e-1f);
    p = fmaf(p, g, 0.5f);
    p = fmaf(p, g, 1.0f);
    p = fmaf(p, g, 1.0f);
    return p * __int_as_float((n << 23) + 0x3F800000);
}

#define CP_ASYNC16(sm, gp) \
    asm volatile("cp.async.cg.shared.global [%0], [%1], 16;" :: "r"(sm), "l"(gp))
#define CP_COMMIT() asm volatile("cp.async.commit_group;")
#define CP_WAIT1()  asm volatile("cp.async.wait_group 1;")

// ---------------------------------------------------------------------------
// Fused prep: X -> fp16 single; W -> fp16 hi/lo.
// ---------------------------------------------------------------------------
#define NX4 (MTOT*DIM/4)
#define NW4 (DIM*DIM/4)
#define NPREP (2*NX4 + 4*NW4)

__device__ __forceinline__ void cast_h(
    const float4* __restrict__ x, uint2* __restrict__ h, int i)
{
    float4 v = x[i];
    union { __half b[4]; uint2 u; } H;
    H.b[0] = __float2half_rn(v.x);
    H.b[1] = __float2half_rn(v.y);
    H.b[2] = __float2half_rn(v.z);
    H.b[3] = __float2half_rn(v.w);
    h[i] = H.u;
}
__device__ __forceinline__ void split_h(
    const float4* __restrict__ x, uint2* __restrict__ h, uint2* __restrict__ l, int i)
{
    float4 v = x[i];
    union { __half b[4]; uint2 u; } H, L;
    H.b[0] = __float2half_rn(v.x);
    H.b[1] = __float2half_rn(v.y);
    H.b[2] = __float2half_rn(v.z);
    H.b[3] = __float2half_rn(v.w);
    L.b[0] = __float2half_rn(v.x - __half2float(H.b[0]));
    L.b[1] = __float2half_rn(v.y - __half2float(H.b[1]));
    L.b[2] = __float2half_rn(v.z - __half2float(H.b[2]));
    L.b[3] = __float2half_rn(v.w - __half2float(H.b[3]));
    h[i] = H.u;
    l[i] = L.u;
}

__global__ __launch_bounds__(256) void prep_split(
    const float4* __restrict__ Xt, const float4* __restrict__ Xf,
    const float4* __restrict__ Wq, const float4* __restrict__ Wk,
    const float4* __restrict__ Wv, const float4* __restrict__ Wo)
{
    int i = blockIdx.x * 256 + threadIdx.x;
    if (i < NX4) {
        cast_h(Xt, (uint2*)g_Xt16, i);
    } else if (i < 2*NX4) {
        cast_h(Xf, (uint2*)g_Xf16, i - NX4);
    } else {
        int j = i - 2*NX4;
        if (j < NW4)           split_h(Wq, (uint2*)g_WqH, (uint2*)g_WqL, j);
        else if (j < 2*NW4)    split_h(Wv, (uint2*)g_WvH, (uint2*)g_WvL, j - NW4);
        else if (j < 3*NW4)    split_h(Wk, (uint2*)g_WkH, (uint2*)g_WkL, j - 2*NW4);
        else if (j < 4*NW4)    split_h(Wo, (uint2*)g_WoH, (uint2*)g_WoL, j - 3*NW4);
    }
}

__global__ __launch_bounds__(256) void pack_mask(
    const int* __restrict__ m, uint32_t* __restrict__ bits)
{
    int i = blockIdx.x * 256 + threadIdx.x;
    unsigned v = __ballot_sync(0xffffffffu, m[i] != 0);
    if ((threadIdx.x & 31) == 0) bits[i >> 5] = v;
}

// ---------------------------------------------------------------------------
// fp16 2-term GEMM: C = A·(Bh+Bl)^T + bias. A single fp16, B hi/lo fp16.
// 3-stage single-sync, 64B rows + XOR swizzle. 2 mma/k16.
// ---------------------------------------------------------------------------
#define BM 128
#define BN 128
#define BK 32
#define TSZB 8192
#define VSSTGB (3*TSZB)          // A, Bh, Bl per stage
#define VGEMM_SMEM (3*VSSTGB)    // 73728 bytes

__device__ __forceinline__ void vgemm_issue(
    const __half* sA, const __half* sBh, const __half* sBl,
    int kc, uint32_t sstage, int tid)
{
    const __half* src[3] = { sA, sBh, sBl };
#pragma unroll
    for (int t = 0; t < 3; t++) {
#pragma unroll
        for (int j = 0; j < 2; j++) {
            int idx = tid + j * 256;
            int r = idx >> 2, c = idx & 3;
            int cs = c ^ ((r >> 1) & 3);
            CP_ASYNC16(sstage + t * TSZB + r * 64 + cs * 16,
                       src[t] + (size_t)r * DIM + kc * BK + c * 8);
        }
    }
}

__global__ __launch_bounds__(256, 2) void gemm_f16_2t(
    const __half* __restrict__ A,
    const __half* __restrict__ Bh, const __half* __restrict__ Bl,
    const float* __restrict__ bias, float* __restrict__ C,
    __half* __restrict__ CH)
{
    extern __shared__ __half smh[];
    const int tid = threadIdx.x, wid = tid >> 5, lane = tid & 31;
    const int bm = blockIdx.y * BM, bn = blockIdx.x * BN;
    const int wm = (wid & 1) * 64, wn = (wid >> 1) * 32;

    const __half* sA  = A  + (size_t)bm * DIM;
    const __half* sB0 = Bh + (size_t)bn * DIM;
    const __half* sB1 = Bl + (size_t)bn * DIM;

    float acc[4][4][4];
#pragma unroll
    for (int i = 0; i < 4; i++)
#pragma unroll
        for (int j = 0; j < 4; j++)
#pragma unroll
            for (int k = 0; k < 4; k++) acc[i][j][k] = 0.0f;

    const int seg = lane >> 3, lr = lane & 7;
    const int swz = (lr >> 1) & 3;
    const int a_rowb = (wm + (seg & 1) * 8 + lr) * 64;
    const int cA0 = (((seg >> 1)    ) ^ swz) << 4;
    const int cA1 = (((seg >> 1) + 2) ^ swz) << 4;
    const int b_rowb = (wn + lr) * 64;
    const int cB0 = (((seg & 1)     ) ^ swz) << 4;
    const int cB1 = (((seg & 1) + 2) ^ swz) << 4;

    const uint32_t sb = smem_u32(smh);

    vgemm_issue(sA, sB0, sB1, 0, sb, tid);           CP_COMMIT();
    vgemm_issue(sA, sB0, sB1, 1, sb + VSSTGB, tid);  CP_COMMIT();
    CP_WAIT1();
    __syncthreads();

    for (int kc = 0; kc < DIM / BK; kc++) {
        if (kc + 2 < DIM / BK)
            vgemm_issue(sA, sB0, sB1, kc + 2,
                        sb + ((kc + 2) % 3) * VSSTGB, tid);
        CP_COMMIT();

        const uint32_t st = sb + (kc % 3) * VSSTGB;
#pragma unroll
        for (int ks = 0; ks < 2; ks++) {
            const int cA = ks ? cA1 : cA0;
            const int cB = ks ? cB1 : cB0;
            uint32_t bh[4][2], bl[4][2];
#pragma unroll
            for (int nt = 0; nt < 4; nt++) {
                uint32_t ad = st + TSZB + b_rowb + nt * (8 * 64) + cB;
                ldsm2(bh[nt], ad);
                ldsm2(bl[nt], ad + TSZB);
            }
#pragma unroll
            for (int mt = 0; mt < 4; mt++) {
                uint32_t ah[4];
                ldsm4(ah, st + a_rowb + mt * (16 * 64) + cA);
#pragma unroll
                for (int nt = 0; nt < 4; nt++) {
                    mma_h16(acc[mt][nt], ah, bh[nt]);
                    mma_h16(acc[mt][nt], ah, bl[nt]);
                }
            }
        }

        CP_WAIT1();
        __syncthreads();
    }

    const int gr = lane >> 2, gc = (lane & 3) * 2;
#pragma unroll
    for (int mt = 0; mt < 4; mt++) {
#pragma unroll
        for (int nt = 0; nt < 4; nt++) {
            int col  = bn + wn + nt * 8 + gc;
            float b0 = bias[col], b1 = bias[col + 1];
            size_t r0 = (size_t)(bm + wm + mt * 16 + gr) * DIM + col;
            size_t r1 = r0 + 8 * DIM;
            float v0 = acc[mt][nt][0] + b0, v1 = acc[mt][nt][1] + b1;
            float v2 = acc[mt][nt][2] + b0, v3 = acc[mt][nt][3] + b1;
            if (CH) {
                *(uint32_t*)&CH[r0] = packh(v1, v0);
                *(uint32_t*)&CH[r1] = packh(v3, v2);
            } else {
                float2 w0 = { v0, v1 }, w1 = { v2, v3 };
                *(float2*)&C[r0] = w0;
                *(float2*)&C[r1] = w1;
            }
        }
    }
}

// ---------------------------------------------------------------------------
// Tensor-core flash attention: QK^T single-term fp16, P·V single-term fp16.
// FT=64, 3-stage single-sync KV pipeline. KV stage = {K, V fp16 single}.
// ---------------------------------------------------------------------------
#define ALD 72
#define SQ0 0
#define SKV0 9216
#define KVARR 4608
#define KVSTG (2*KVARR)
#define ATT_SMEM ((SKV0 + 3*KVSTG)*2)   // 73728 bytes

__device__ __forceinline__ void kv_issue(
    const __half* K, const __half* V,
    size_t gfrow, int hof, uint32_t stbase, int tid)
{
#pragma unroll
    for (int j = 0; j < 2; j++) {
        int idx = tid + j * 256;
        int r = idx >> 3, c = (idx & 7) * 8;
        size_t g = (gfrow + r) * DIM + hof + c;
        uint32_t so = stbase + (r * ALD + c) * 2;
        CP_ASYNC16(so,             K + g);
        CP_ASYNC16(so + KVARR * 2, V + g);
    }
}

__global__ __launch_bounds__(256, 1) void attn_mma(
    const __half* __restrict__ Q, const __half* __restrict__ K,
    const __half* __restrict__ V,
    const uint32_t* __restrict__ mbits,
    __half* __restrict__ AHo)
{
    extern __shared__ __half sm[];
    const int tid = threadIdx.x, w = tid >> 5, lane = tid & 31;
    const int t0 = blockIdx.x * 128, h = blockIdx.y, b = blockIdx.z;
    const int lr = lane & 7, seg = lane >> 3;
    const int gr = lane >> 2, qc = (lane & 3) * 2;
    const uint32_t sb = smem_u32(sm);
    const int hof = h * HD;
    const size_t gfbase = (size_t)(b * GF);

    kv_issue(K, V, gfbase,      hof, sb + SKV0 * 2, tid);           CP_COMMIT();
    kv_issue(K, V, gfbase + 64, hof, sb + (SKV0 + KVSTG) * 2, tid); CP_COMMIT();

    // Load Q tile (fp16 single)
    {
        const size_t grow = (size_t)(b * GT + t0);
#pragma unroll
        for (int j = 0; j < 4; j++) {
            int idx = tid + j * 256;
            int r = idx >> 3, c = (idx & 7) * 8;
            *(uint4*)&sm[SQ0 + r * ALD + c] =
                *(const uint4*)&Q[(grow + r) * DIM + hof + c];
        }
    }
    CP_WAIT1();
    __syncthreads();

    uint32_t qh[4][4];
#pragma unroll
    for (int kc = 0; kc < 4; kc++) {
        uint32_t ad = sb + ((w * 16 + (seg & 1) * 8 + lr) * ALD + kc * 16 + (seg >> 1) * 8) * 2;
        ldsm4(qh[kc], ad + SQ0 * 2);
    }

    float oacc[8][4];
#pragma unroll
    for (int i = 0; i < 8; i++)
#pragma unroll
        for (int j = 0; j < 4; j++) oacc[i][j] = 0.0f;
    float m0 = -1e30f, m1 = -1e30f, l0 = 0.0f, l1 = 0.0f;

    const int mrow0 = b * GT + t0 + w * 16 + gr;
    const uint32_t* mrp0 = mbits + (size_t)mrow0 * (GF / 32);
    const uint32_t* mrp1 = mrp0 + 8 * (GF / 32);

    for (int ftile = 0; ftile < 16; ftile++) {
        if (ftile + 2 < 16)
            kv_issue(K, V, gfbase + (ftile + 2) * 64, hof,
                     sb + (SKV0 + ((ftile + 2) % 3) * KVSTG) * 2, tid);
        CP_COMMIT();

        const uint32_t stg = SKV0 + (ftile % 3) * KVSTG;

        uint2 mw0 = *(const uint2*)(mrp0 + ftile * 2);
        uint2 mw1 = *(const uint2*)(mrp1 + ftile * 2);
        uint32_t wA[2] = { mw0.x, mw0.y };
        uint32_t wB[2] = { mw1.x, mw1.y };

        // S = Q K^T (fp16 single-term)
        float sacc[8][4];
#pragma unroll
        for (int nt = 0; nt < 8; nt++) {
#pragma unroll
            for (int j = 0; j < 4; j++) sacc[nt][j] = 0.0f;
        }
#pragma unroll
        for (int nt = 0; nt < 8; nt++) {
            uint32_t bh[8];
#pragma unroll
            for (int kcg = 0; kcg < 2; kcg++) {
                uint32_t ad = sb + (stg + (nt * 8 + lr) * ALD + kcg * 32 + seg * 8) * 2;
                ldsm4(&bh[kcg * 4], ad);
            }
#pragma unroll
            for (int kc = 0; kc < 4; kc++)
                mma_h16(sacc[nt], qh[kc], &bh[kc * 2]);
        }

        // mask + scale + row max
        float rm0 = -1e30f, rm1 = -1e30f;
#pragma unroll
        for (int nt = 0; nt < 8; nt++) {
            uint32_t sh = (nt & 3) * 8 + qc;
            uint32_t bA = wA[nt >> 2] >> sh;
            uint32_t bB = wB[nt >> 2] >> sh;
            float s0 = (bA & 1u) ? sacc[nt][0] * 0.125f : -10000.0f;
            float s1 = (bA & 2u) ? sacc[nt][1] * 0.125f : -10000.0f;
            float s2 = (bB & 1u) ? sacc[nt][2] * 0.125f : -10000.0f;
            float s3 = (bB & 2u) ? sacc[nt][3] * 0.125f : -10000.0f;
            sacc[nt][0] = s0; sacc[nt][1] = s1; sacc[nt][2] = s2; sacc[nt][3] = s3;
            rm0 = fmaxf(rm0, fmaxf(s0, s1));
            rm1 = fmaxf(rm1, fmaxf(s2, s3));
        }
        rm0 = fmaxf(rm0, __shfl_xor_sync(0xffffffffu, rm0, 1));
        rm0 = fmaxf(rm0, __shfl_xor_sync(0xffffffffu, rm0, 2));
        rm1 = fmaxf(rm1, __shfl_xor_sync(0xffffffffu, rm1, 1));
        rm1 = fmaxf(rm1, __shfl_xor_sync(0xffffffffu, rm1, 2));
        float mn0 = fmaxf(m0, rm0), mn1 = fmaxf(m1, rm1);
        float c0 = fast_exp(m0 - mn0), c1 = fast_exp(m1 - mn1);
        m0 = mn0; m1 = mn1;

        // P = exp(s-m), pack fp16, row sums
        uint32_t pah[4][4];
        float rs0 = 0.0f, rs1 = 0.0f;
#pragma unroll
        for (int kc = 0; kc < 4; kc++) {
            float p0 = fast_exp(sacc[2*kc][0] - m0);
            float p1 = fast_exp(sacc[2*kc][1] - m0);
            float p2 = fast_exp(sacc[2*kc][2] - m1);
            float p3 = fast_exp(sacc[2*kc][3] - m1);
            float p4 = fast_exp(sacc[2*kc+1][0] - m0);
            float p5 = fast_exp(sacc[2*kc+1][1] - m0);
            float p6 = fast_exp(sacc[2*kc+1][2] - m1);
            float p7 = fast_exp(sacc[2*kc+1][3] - m1);
            rs0 += (p0 + p1) + (p4 + p5);
            rs1 += (p2 + p3) + (p6 + p7);
            pah[kc][0] = packh(p1, p0);
            pah[kc][1] = packh(p3, p2);
            pah[kc][2] = packh(p5, p4);
            pah[kc][3] = packh(p7, p6);
        }
        rs0 += __shfl_xor_sync(0xffffffffu, rs0, 1);
        rs0 += __shfl_xor_sync(0xffffffffu, rs0, 2);
        rs1 += __shfl_xor_sync(0xffffffffu, rs1, 1);
        rs1 += __shfl_xor_sync(0xffffffffu, rs1, 2);
        l0 = l0 * c0 + rs0;
        l1 = l1 * c1 + rs1;

#pragma unroll
        for (int nt = 0; nt < 8; nt++) {
            oacc[nt][0] *= c0; oacc[nt][1] *= c0;
            oacc[nt][2] *= c1; oacc[nt][3] *= c1;
        }

        // O += P V (fp16 single-term)
#pragma unroll
        for (int kcg = 0; kcg < 2; kcg++) {
#pragma unroll
            for (int nt = 0; nt < 8; nt++) {
                uint32_t bvh[4];
                uint32_t ad = sb + (stg + KVARR + (kcg * 32 + seg * 8 + lr) * ALD + nt * 8) * 2;
                ldsm4t(bvh, ad);
                mma_h16(oacc[nt], pah[2*kcg],   &bvh[0]);
                mma_h16(oacc[nt], pah[2*kcg+1], &bvh[2]);
            }
        }

        CP_WAIT1();
        __syncthreads();
    }

    // Epilogue: fp16 output
    float inv0 = 1.0f / l0, inv1 = 1.0f / l1;
    size_t orow = (size_t)(b * GT + t0 + w * 16 + gr) * DIM + hof;
#pragma unroll
    for (int nt = 0; nt < 8; nt++) {
        int col = nt * 8 + qc;
        float v0 = oacc[nt][0] * inv0, v1 = oacc[nt][1] * inv0;
        float v2 = oacc[nt][2] * inv1, v3 = oacc[nt][3] * inv1;
        *(uint32_t*)&AHo[orow + col] = packh(v1, v0);
        *(uint32_t*)&AHo[orow + 8 * DIM + col] = packh(v3, v2);
    }
}

// ---------------------------------------------------------------------------
// Launch
// ---------------------------------------------------------------------------
extern "C" void kernel_launch(void* const* d_in, const int* in_sizes, int n_in,
                              void* d_out, int out_size)
{
    const float* X_to   = (const float*)d_in[0];
    const float* X_from = (const float*)d_in[1];
    const int*   maskp  = (const int*)  d_in[2];
    const float* Wq = (const float*)d_in[3];
    const float* bq = (const float*)d_in[4];
    const float* Wk = (const float*)d_in[5];
    const float* bk = (const float*)d_in[6];
    const float* Wv = (const float*)d_in[7];
    const float* bv = (const float*)d_in[8];
    const float* Wo = (const float*)d_in[9];
    const float* bo = (const float*)d_in[10];
    float* out = (float*)d_out;

    __half *Q,*K,*V,*A,*Xt16,*Xf16;
    __half *WqH,*WqL,*WkH,*WkL,*WvH,*WvL,*WoH,*WoL;
    uint32_t* mbits;
    cudaGetSymbolAddress((void**)&Q, g_Q);
    cudaGetSymbolAddress((void**)&K, g_K);
    cudaGetSymbolAddress((void**)&V, g_V);
    cudaGetSymbolAddress((void**)&A, g_A);
    cudaGetSymbolAddress((void**)&Xt16, g_Xt16);
    cudaGetSymbolAddress((void**)&Xf16, g_Xf16);
    cudaGetSymbolAddress((void**)&WqH, g_WqH); cudaGetSymbolAddress((void**)&WqL, g_WqL);
    cudaGetSymbolAddress((void**)&WkH, g_WkH); cudaGetSymbolAddress((void**)&WkL, g_WkL);
    cudaGetSymbolAddress((void**)&WvH, g_WvH); cudaGetSymbolAddress((void**)&WvL, g_WvL);
    cudaGetSymbolAddress((void**)&WoH, g_WoH); cudaGetSymbolAddress((void**)&WoL, g_WoL);
    cudaGetSymbolAddress((void**)&mbits, g_mbits);

    cudaFuncSetAttribute(gemm_f16_2t,
                         cudaFuncAttributeMaxDynamicSharedMemorySize, VGEMM_SMEM);
    cudaFuncSetAttribute(attn_mma,
                         cudaFuncAttributeMaxDynamicSharedMemorySize, ATT_SMEM);

    prep_split<<<NPREP / 256, 256>>>((const float4*)X_to, (const float4*)X_from,
                                     (const float4*)Wq, (const float4*)Wk,
                                     (const float4*)Wv, (const float4*)Wo);
    pack_mask<<<(MTOT * GF) / 256, 256>>>(maskp, mbits);

    dim3 gg(DIM / BN, MTOT / BM);   // (8, 32)

    // Projections (fp16 2-term). NOTE reference's swap: K <= Wv/bv, V <= Wk/bk.
    gemm_f16_2t<<<gg, 256, VGEMM_SMEM>>>(Xt16, WqH, WqL, bq, nullptr, Q);
    gemm_f16_2t<<<gg, 256, VGEMM_SMEM>>>(Xf16, WvH, WvL, bv, nullptr, K);
    gemm_f16_2t<<<gg, 256, VGEMM_SMEM>>>(Xf16, WkH, WkL, bk, nullptr, V);

    dim3 ag(GT / 128, GH, GB);      // (8, 16, 4)
    attn_mma<<<ag, 256, ATT_SMEM>>>(Q, K, V, mbits, A);

    // Output projection (fp16 2-term, fp32 out)
    gemm_f16_2t<<<gg, 256, VGEMM_SMEM>>>(A, WoH, WoL, bo, out, nullptr);
}

// round 13
// speedup vs baseline: 2.2346x; 1.2475x over previous
#include <cuda_runtime.h>
#include <cuda_fp16.h>
#include <cstdint>
#include <math.h>

// Problem constants
#define GB 4
#define GT 1024
#define GF 1024
#define DIM 1024
#define GH 16
#define HD 64
#define MTOT (GB*GT)   // 4096

// ---------------------------------------------------------------------------
// Scratch (__device__ globals; allocation-free rule)
// ---------------------------------------------------------------------------
__device__ __half g_Q[MTOT*DIM];
__device__ __half g_K[MTOT*DIM];
__device__ __half g_V[MTOT*DIM];
__device__ __half g_A[MTOT*DIM];
__device__ __half g_Xt16[MTOT*DIM];
__device__ __half g_Xf16[MTOT*DIM];
__device__ __half g_Wq16[DIM*DIM];
__device__ __half g_Wk16[DIM*DIM];
__device__ __half g_Wv16[DIM*DIM];
__device__ __half g_Wo16[DIM*DIM];
__device__ uint32_t g_mbits[MTOT*GF/32];

// ---------------------------------------------------------------------------
// Helpers
// ---------------------------------------------------------------------------
__device__ __forceinline__ uint32_t smem_u32(const void* p){
    uint32_t a;
    asm("{ .reg .u64 t; cvta.to.shared.u64 t, %1; cvt.u32.u64 %0, t; }"
        : "=r"(a) : "l"(p));
    return a;
}
__device__ __forceinline__ void ldsm4(uint32_t* r, uint32_t addr){
    asm volatile("ldmatrix.sync.aligned.m8n8.x4.shared.b16 {%0,%1,%2,%3}, [%4];"
        : "=r"(r[0]), "=r"(r[1]), "=r"(r[2]), "=r"(r[3]) : "r"(addr));
}
__device__ __forceinline__ void ldsm2(uint32_t* r, uint32_t addr){
    asm volatile("ldmatrix.sync.aligned.m8n8.x2.shared.b16 {%0,%1}, [%2];"
        : "=r"(r[0]), "=r"(r[1]) : "r"(addr));
}
__device__ __forceinline__ void ldsm4t(uint32_t* r, uint32_t addr){
    asm volatile("ldmatrix.sync.aligned.m8n8.x4.trans.shared.b16 {%0,%1,%2,%3}, [%4];"
        : "=r"(r[0]), "=r"(r[1]), "=r"(r[2]), "=r"(r[3]) : "r"(addr));
}
__device__ __forceinline__ void mma_h16(float* d, const uint32_t* a, const uint32_t* b){
    asm volatile("mma.sync.aligned.m16n8k16.row.col.f32.f16.f16.f32 "
        "{%0,%1,%2,%3}, {%4,%5,%6,%7}, {%8,%9}, {%0,%1,%2,%3};"
        : "+f"(d[0]), "+f"(d[1]), "+f"(d[2]), "+f"(d[3])
        : "r"(a[0]), "r"(a[1]), "r"(a[2]), "r"(a[3]), "r"(b[0]), "r"(b[1]));
}
__device__ __forceinline__ uint32_t packh(float hi, float lo){
    uint32_t r;
    asm("cvt.rn.f16x2.f32 %0, %1, %2;" : "=r"(r) : "f"(hi), "f"(lo));
    return r;
}

// Branch-free exp on FMA/ALU pipes only.
__device__ __forceinline__ float fast_exp(float x){
    float xc = fmaxf(x, -87.0f);
    float r  = fmaf(xc, 1.4426950408889634f, 12582912.0f);
    int   n  = __float_as_int(r) - 0x4B400000;
    float fi = r - 12582912.0f;
    float g  = fmaf(fi, -0.6931471805599453f, xc);
    float p  = 8.3333337e-3f;
    p = fmaf(p, g, 4.1666668e-2f);
    p = fmaf(p, g, 1.6666667e-1f);
    p = fmaf(p, g, 0.5f);
    p = fmaf(p, g, 1.0f);
    p = fmaf(p, g, 1.0f);
    return p * __int_as_float((n << 23) + 0x3F800000);
}

#define CP_ASYNC16(sm, gp) \
    asm volatile("cp.async.cg.shared.global [%0], [%1], 16;" :: "r"(sm), "l"(gp))
#define CP_COMMIT() asm volatile("cp.async.commit_group;")
#define CP_WAIT1()  asm volatile("cp.async.wait_group 1;")

// ---------------------------------------------------------------------------
// Fused prep: all fp32 -> fp16 single casts in one launch.
// ---------------------------------------------------------------------------
#define NX4 (MTOT*DIM/4)
#define NW4 (DIM*DIM/4)
#define NPREP (2*NX4 + 4*NW4)

__device__ __forceinline__ void cast_h(
    const float4* __restrict__ x, uint2* __restrict__ h, int i)
{
    float4 v = x[i];
    union { __half b[4]; uint2 u; } H;
    H.b[0] = __float2half_rn(v.x);
    H.b[1] = __float2half_rn(v.y);
    H.b[2] = __float2half_rn(v.z);
    H.b[3] = __float2half_rn(v.w);
    h[i] = H.u;
}

__global__ __launch_bounds__(256) void prep_cast(
    const float4* __restrict__ Xt, const float4* __restrict__ Xf,
    const float4* __restrict__ Wq, const float4* __restrict__ Wk,
    const float4* __restrict__ Wv, const float4* __restrict__ Wo)
{
    int i = blockIdx.x * 256 + threadIdx.x;
    if (i < NX4) {
        cast_h(Xt, (uint2*)g_Xt16, i);
    } else if (i < 2*NX4) {
        cast_h(Xf, (uint2*)g_Xf16, i - NX4);
    } else {
        int j = i - 2*NX4;
        if (j < NW4)           cast_h(Wq, (uint2*)g_Wq16, j);
        else if (j < 2*NW4)    cast_h(Wv, (uint2*)g_Wv16, j - NW4);
        else if (j < 3*NW4)    cast_h(Wk, (uint2*)g_Wk16, j - 2*NW4);
        else if (j < 4*NW4)    cast_h(Wo, (uint2*)g_Wo16, j - 3*NW4);
    }
}

__global__ __launch_bounds__(256) void pack_mask(
    const int* __restrict__ m, uint32_t* __restrict__ bits)
{
    int i = blockIdx.x * 256 + threadIdx.x;
    unsigned v = __ballot_sync(0xffffffffu, m[i] != 0);
    if ((threadIdx.x & 31) == 0) bits[i >> 5] = v;
}

// ---------------------------------------------------------------------------
// fp16 1-term GEMM: C = A·B^T + bias. 1 mma/k16.
// 3-stage single-sync, 64B rows + XOR swizzle.
// ---------------------------------------------------------------------------
#define BM 128
#define BN 128
#define BK 32
#define TSZB 8192
#define GSTGB (2*TSZB)          // A, B per stage = 16384 bytes
#define GEMM_SMEM (3*GSTGB)     // 49152 bytes

__device__ __forceinline__ void gemm_issue(
    const __half* sA, const __half* sB,
    int kc, uint32_t sstage, int tid)
{
    const __half* src[2] = { sA, sB };
#pragma unroll
    for (int t = 0; t < 2; t++) {
#pragma unroll
        for (int j = 0; j < 2; j++) {
            int idx = tid + j * 256;
            int r = idx >> 2, c = idx & 3;
            int cs = c ^ ((r >> 1) & 3);
            CP_ASYNC16(sstage + t * TSZB + r * 64 + cs * 16,
                       src[t] + (size_t)r * DIM + kc * BK + c * 8);
        }
    }
}

__global__ __launch_bounds__(256, 2) void gemm_f16(
    const __half* __restrict__ A, const __half* __restrict__ B,
    const float* __restrict__ bias, float* __restrict__ C,
    __half* __restrict__ CH)
{
    extern __shared__ __half smh[];
    const int tid = threadIdx.x, wid = tid >> 5, lane = tid & 31;
    const int bm = blockIdx.y * BM, bn = blockIdx.x * BN;
    const int wm = (wid & 1) * 64, wn = (wid >> 1) * 32;

    const __half* sA = A + (size_t)bm * DIM;
    const __half* sB = B + (size_t)bn * DIM;

    float acc[4][4][4];
#pragma unroll
    for (int i = 0; i < 4; i++)
#pragma unroll
        for (int j = 0; j < 4; j++)
#pragma unroll
            for (int k = 0; k < 4; k++) acc[i][j][k] = 0.0f;

    const int seg = lane >> 3, lr = lane & 7;
    const int swz = (lr >> 1) & 3;
    const int a_rowb = (wm + (seg & 1) * 8 + lr) * 64;
    const int cA0 = (((seg >> 1)    ) ^ swz) << 4;
    const int cA1 = (((seg >> 1) + 2) ^ swz) << 4;
    const int b_rowb = (wn + lr) * 64;
    const int cB0 = (((seg & 1)     ) ^ swz) << 4;
    const int cB1 = (((seg & 1) + 2) ^ swz) << 4;

    const uint32_t sb = smem_u32(smh);

    gemm_issue(sA, sB, 0, sb, tid);          CP_COMMIT();
    gemm_issue(sA, sB, 1, sb + GSTGB, tid);  CP_COMMIT();
    CP_WAIT1();
    __syncthreads();

    for (int kc = 0; kc < DIM / BK; kc++) {
        if (kc + 2 < DIM / BK)
            gemm_issue(sA, sB, kc + 2, sb + ((kc + 2) % 3) * GSTGB, tid);
        CP_COMMIT();

        const uint32_t st = sb + (kc % 3) * GSTGB;
#pragma unroll
        for (int ks = 0; ks < 2; ks++) {
            const int cA = ks ? cA1 : cA0;
            const int cB = ks ? cB1 : cB0;
            uint32_t bh[4][2];
#pragma unroll
            for (int nt = 0; nt < 4; nt++)
                ldsm2(bh[nt], st + TSZB + b_rowb + nt * (8 * 64) + cB);
#pragma unroll
            for (int mt = 0; mt < 4; mt++) {
                uint32_t ah[4];
                ldsm4(ah, st + a_rowb + mt * (16 * 64) + cA);
#pragma unroll
                for (int nt = 0; nt < 4; nt++)
                    mma_h16(acc[mt][nt], ah, bh[nt]);
            }
        }

        CP_WAIT1();
        __syncthreads();
    }

    const int gr = lane >> 2, gc = (lane & 3) * 2;
#pragma unroll
    for (int mt = 0; mt < 4; mt++) {
#pragma unroll
        for (int nt = 0; nt < 4; nt++) {
            int col  = bn + wn + nt * 8 + gc;
            float b0 = bias[col], b1 = bias[col + 1];
            size_t r0 = (size_t)(bm + wm + mt * 16 + gr) * DIM + col;
            size_t r1 = r0 + 8 * DIM;
            float v0 = acc[mt][nt][0] + b0, v1 = acc[mt][nt][1] + b1;
            float v2 = acc[mt][nt][2] + b0, v3 = acc[mt][nt][3] + b1;
            if (CH) {
                *(uint32_t*)&CH[r0] = packh(v1, v0);
                *(uint32_t*)&CH[r1] = packh(v3, v2);
            } else {
                float2 w0 = { v0, v1 }, w1 = { v2, v3 };
                *(float2*)&C[r0] = w0;
                *(float2*)&C[r1] = w1;
            }
        }
    }
}

// ---------------------------------------------------------------------------
// Tensor-core flash attention: QK^T and P·V single-term fp16 (R12-exact).
// FT=64, 3-stage single-sync KV pipeline.
// ---------------------------------------------------------------------------
#define ALD 72
#define SQ0 0
#define SKV0 9216
#define KVARR 4608
#define KVSTG (2*KVARR)
#define ATT_SMEM ((SKV0 + 3*KVSTG)*2)   // 73728 bytes

__device__ __forceinline__ void kv_issue(
    const __half* K, const __half* V,
    size_t gfrow, int hof, uint32_t stbase, int tid)
{
#pragma unroll
    for (int j = 0; j < 2; j++) {
        int idx = tid + j * 256;
        int r = idx >> 3, c = (idx & 7) * 8;
        size_t g = (gfrow + r) * DIM + hof + c;
        uint32_t so = stbase + (r * ALD + c) * 2;
        CP_ASYNC16(so,             K + g);
        CP_ASYNC16(so + KVARR * 2, V + g);
    }
}

__global__ __launch_bounds__(256, 1) void attn_mma(
    const __half* __restrict__ Q, const __half* __restrict__ K,
    const __half* __restrict__ V,
    const uint32_t* __restrict__ mbits,
    __half* __restrict__ AHo)
{
    extern __shared__ __half sm[];
    const int tid = threadIdx.x, w = tid >> 5, lane = tid & 31;
    const int t0 = blockIdx.x * 128, h = blockIdx.y, b = blockIdx.z;
    const int lr = lane & 7, seg = lane >> 3;
    const int gr = lane >> 2, qc = (lane & 3) * 2;
    const uint32_t sb = smem_u32(sm);
    const int hof = h * HD;
    const size_t gfbase = (size_t)(b * GF);

    kv_issue(K, V, gfbase,      hof, sb + SKV0 * 2, tid);           CP_COMMIT();
    kv_issue(K, V, gfbase + 64, hof, sb + (SKV0 + KVSTG) * 2, tid); CP_COMMIT();

    // Load Q tile
    {
        const size_t grow = (size_t)(b * GT + t0);
#pragma unroll
        for (int j = 0; j < 4; j++) {
            int idx = tid + j * 256;
            int r = idx >> 3, c = (idx & 7) * 8;
            *(uint4*)&sm[SQ0 + r * ALD + c] =
                *(const uint4*)&Q[(grow + r) * DIM + hof + c];
        }
    }
    CP_WAIT1();
    __syncthreads();

    uint32_t qh[4][4];
#pragma unroll
    for (int kc = 0; kc < 4; kc++) {
        uint32_t ad = sb + ((w * 16 + (seg & 1) * 8 + lr) * ALD + kc * 16 + (seg >> 1) * 8) * 2;
        ldsm4(qh[kc], ad + SQ0 * 2);
    }

    float oacc[8][4];
#pragma unroll
    for (int i = 0; i < 8; i++)
#pragma unroll
        for (int j = 0; j < 4; j++) oacc[i][j] = 0.0f;
    float m0 = -1e30f, m1 = -1e30f, l0 = 0.0f, l1 = 0.0f;

    const int mrow0 = b * GT + t0 + w * 16 + gr;
    const uint32_t* mrp0 = mbits + (size_t)mrow0 * (GF / 32);
    const uint32_t* mrp1 = mrp0 + 8 * (GF / 32);

    for (int ftile = 0; ftile < 16; ftile++) {
        if (ftile + 2 < 16)
            kv_issue(K, V, gfbase + (ftile + 2) * 64, hof,
                     sb + (SKV0 + ((ftile + 2) % 3) * KVSTG) * 2, tid);
        CP_COMMIT();

        const uint32_t stg = SKV0 + (ftile % 3) * KVSTG;

        uint2 mw0 = *(const uint2*)(mrp0 + ftile * 2);
        uint2 mw1 = *(const uint2*)(mrp1 + ftile * 2);
        uint32_t wA[2] = { mw0.x, mw0.y };
        uint32_t wB[2] = { mw1.x, mw1.y };

        // S = Q K^T
        float sacc[8][4];
#pragma unroll
        for (int nt = 0; nt < 8; nt++) {
#pragma unroll
            for (int j = 0; j < 4; j++) sacc[nt][j] = 0.0f;
        }
#pragma unroll
        for (int nt = 0; nt < 8; nt++) {
            uint32_t bh[8];
#pragma unroll
            for (int kcg = 0; kcg < 2; kcg++) {
                uint32_t ad = sb + (stg + (nt * 8 + lr) * ALD + kcg * 32 + seg * 8) * 2;
                ldsm4(&bh[kcg * 4], ad);
            }
#pragma unroll
            for (int kc = 0; kc < 4; kc++)
                mma_h16(sacc[nt], qh[kc], &bh[kc * 2]);
        }

        // mask + scale + row max
        float rm0 = -1e30f, rm1 = -1e30f;
#pragma unroll
        for (int nt = 0; nt < 8; nt++) {
            uint32_t sh = (nt & 3) * 8 + qc;
            uint32_t bA = wA[nt >> 2] >> sh;
            uint32_t bB = wB[nt >> 2] >> sh;
            float s0 = (bA & 1u) ? sacc[nt][0] * 0.125f : -10000.0f;
            float s1 = (bA & 2u) ? sacc[nt][1] * 0.125f : -10000.0f;
            float s2 = (bB & 1u) ? sacc[nt][2] * 0.125f : -10000.0f;
            float s3 = (bB & 2u) ? sacc[nt][3] * 0.125f : -10000.0f;
            sacc[nt][0] = s0; sacc[nt][1] = s1; sacc[nt][2] = s2; sacc[nt][3] = s3;
            rm0 = fmaxf(rm0, fmaxf(s0, s1));
            rm1 = fmaxf(rm1, fmaxf(s2, s3));
        }
        rm0 = fmaxf(rm0, __shfl_xor_sync(0xffffffffu, rm0, 1));
        rm0 = fmaxf(rm0, __shfl_xor_sync(0xffffffffu, rm0, 2));
        rm1 = fmaxf(rm1, __shfl_xor_sync(0xffffffffu, rm1, 1));
        rm1 = fmaxf(rm1, __shfl_xor_sync(0xffffffffu, rm1, 2));
        float mn0 = fmaxf(m0, rm0), mn1 = fmaxf(m1, rm1);
        float c0 = fast_exp(m0 - mn0), c1 = fast_exp(m1 - mn1);
        m0 = mn0; m1 = mn1;

        // P = exp(s-m), pack fp16, row sums
        uint32_t pah[4][4];
        float rs0 = 0.0f, rs1 = 0.0f;
#pragma unroll
        for (int kc = 0; kc < 4; kc++) {
            float p0 = fast_exp(sacc[2*kc][0] - m0);
            float p1 = fast_exp(sacc[2*kc][1] - m0);
            float p2 = fast_exp(sacc[2*kc][2] - m1);
            float p3 = fast_exp(sacc[2*kc][3] - m1);
            float p4 = fast_exp(sacc[2*kc+1][0] - m0);
            float p5 = fast_exp(sacc[2*kc+1][1] - m0);
            float p6 = fast_exp(sacc[2*kc+1][2] - m1);
            float p7 = fast_exp(sacc[2*kc+1][3] - m1);
            rs0 += (p0 + p1) + (p4 + p5);
            rs1 += (p2 + p3) + (p6 + p7);
            pah[kc][0] = packh(p1, p0);
            pah[kc][1] = packh(p3, p2);
            pah[kc][2] = packh(p5, p4);
            pah[kc][3] = packh(p7, p6);
        }
        rs0 += __shfl_xor_sync(0xffffffffu, rs0, 1);
        rs0 += __shfl_xor_sync(0xffffffffu, rs0, 2);
        rs1 += __shfl_xor_sync(0xffffffffu, rs1, 1);
        rs1 += __shfl_xor_sync(0xffffffffu, rs1, 2);
        l0 = l0 * c0 + rs0;
        l1 = l1 * c1 + rs1;

#pragma unroll
        for (int nt = 0; nt < 8; nt++) {
            oacc[nt][0] *= c0; oacc[nt][1] *= c0;
            oacc[nt][2] *= c1; oacc[nt][3] *= c1;
        }

        // O += P V
#pragma unroll
        for (int kcg = 0; kcg < 2; kcg++) {
#pragma unroll
            for (int nt = 0; nt < 8; nt++) {
                uint32_t bvh[4];
                uint32_t ad = sb + (stg + KVARR + (kcg * 32 + seg * 8 + lr) * ALD + nt * 8) * 2;
                ldsm4t(bvh, ad);
                mma_h16(oacc[nt], pah[2*kcg],   &bvh[0]);
                mma_h16(oacc[nt], pah[2*kcg+1], &bvh[2]);
            }
        }

        CP_WAIT1();
        __syncthreads();
    }

    // Epilogue: fp16 output
    float inv0 = 1.0f / l0, inv1 = 1.0f / l1;
    size_t orow = (size_t)(b * GT + t0 + w * 16 + gr) * DIM + hof;
#pragma unroll
    for (int nt = 0; nt < 8; nt++) {
        int col = nt * 8 + qc;
        float v0 = oacc[nt][0] * inv0, v1 = oacc[nt][1] * inv0;
        float v2 = oacc[nt][2] * inv1, v3 = oacc[nt][3] * inv1;
        *(uint32_t*)&AHo[orow + col] = packh(v1, v0);
        *(uint32_t*)&AHo[orow + 8 * DIM + col] = packh(v3, v2);
    }
}

// ---------------------------------------------------------------------------
// Launch
// ---------------------------------------------------------------------------
extern "C" void kernel_launch(void* const* d_in, const int* in_sizes, int n_in,
                              void* d_out, int out_size)
{
    const float* X_to   = (const float*)d_in[0];
    const float* X_from = (const float*)d_in[1];
    const int*   maskp  = (const int*)  d_in[2];
    const float* Wq = (const float*)d_in[3];
    const float* bq = (const float*)d_in[4];
    const float* Wk = (const float*)d_in[5];
    const float* bk = (const float*)d_in[6];
    const float* Wv = (const float*)d_in[7];
    const float* bv = (const float*)d_in[8];
    const float* Wo = (const float*)d_in[9];
    const float* bo = (const float*)d_in[10];
    float* out = (float*)d_out;

    __half *Q,*K,*V,*A,*Xt16,*Xf16,*Wq16,*Wk16,*Wv16,*Wo16;
    uint32_t* mbits;
    cudaGetSymbolAddress((void**)&Q, g_Q);
    cudaGetSymbolAddress((void**)&K, g_K);
    cudaGetSymbolAddress((void**)&V, g_V);
    cudaGetSymbolAddress((void**)&A, g_A);
    cudaGetSymbolAddress((void**)&Xt16, g_Xt16);
    cudaGetSymbolAddress((void**)&Xf16, g_Xf16);
    cudaGetSymbolAddress((void**)&Wq16, g_Wq16);
    cudaGetSymbolAddress((void**)&Wk16, g_Wk16);
    cudaGetSymbolAddress((void**)&Wv16, g_Wv16);
    cudaGetSymbolAddress((void**)&Wo16, g_Wo16);
    cudaGetSymbolAddress((void**)&mbits, g_mbits);

    cudaFuncSetAttribute(gemm_f16,
                         cudaFuncAttributeMaxDynamicSharedMemorySize, GEMM_SMEM);
    cudaFuncSetAttribute(attn_mma,
                         cudaFuncAttributeMaxDynamicSharedMemorySize, ATT_SMEM);

    prep_cast<<<NPREP / 256, 256>>>((const float4*)X_to, (const float4*)X_from,
                                    (const float4*)Wq, (const float4*)Wk,
                                    (const float4*)Wv, (const float4*)Wo);
    pack_mask<<<(MTOT * GF) / 256, 256>>>(maskp, mbits);

    dim3 gg(DIM / BN, MTOT / BM);   // (8, 32)

    // Projections (fp16 1-term). NOTE reference's swap: K <= Wv/bv, V <= Wk/bk.
    gemm_f16<<<gg, 256, GEMM_SMEM>>>(Xt16, Wq16, bq, nullptr, Q);
    gemm_f16<<<gg, 256, GEMM_SMEM>>>(Xf16, Wv16, bv, nullptr, K);
    gemm_f16<<<gg, 256, GEMM_SMEM>>>(Xf16, Wk16, bk, nullptr, V);

    dim3 ag(GT / 128, GH, GB);      // (8, 16, 4)
    attn_mma<<<ag, 256, ATT_SMEM>>>(Q, K, V, mbits, A);

    // Output projection (fp16 1-term, fp32 out)
    gemm_f16<<<gg, 256, GEMM_SMEM>>>(A, Wo16, bo, out, nullptr);
}

// round 14
// speedup vs baseline: 2.4324x; 1.0885x over previous
#include <cuda_runtime.h>
#include <cuda_fp16.h>
#include <cstdint>
#include <math.h>

// Problem constants
#define GB 4
#define GT 1024
#define GF 1024
#define DIM 1024
#define GH 16
#define HD 64
#define MTOT (GB*GT)   // 4096

// ---------------------------------------------------------------------------
// Scratch (__device__ globals; allocation-free rule)
// ---------------------------------------------------------------------------
__device__ __half g_Q[MTOT*DIM];
__device__ __half g_K[MTOT*DIM];
__device__ __half g_V[MTOT*DIM];
__device__ __half g_A[MTOT*DIM];
__device__ __half g_Xt16[MTOT*DIM];
__device__ __half g_Xf16[MTOT*DIM];
__device__ __half g_Wq16[DIM*DIM];
__device__ __half g_Wk16[DIM*DIM];
__device__ __half g_Wv16[DIM*DIM];
__device__ __half g_Wo16[DIM*DIM];
__device__ uint32_t g_mbits[MTOT*GF/32];

// ---------------------------------------------------------------------------
// Helpers
// ---------------------------------------------------------------------------
__device__ __forceinline__ uint32_t smem_u32(const void* p){
    uint32_t a;
    asm("{ .reg .u64 t; cvta.to.shared.u64 t, %1; cvt.u32.u64 %0, t; }"
        : "=r"(a) : "l"(p));
    return a;
}
__device__ __forceinline__ void ldsm4(uint32_t* r, uint32_t addr){
    asm volatile("ldmatrix.sync.aligned.m8n8.x4.shared.b16 {%0,%1,%2,%3}, [%4];"
        : "=r"(r[0]), "=r"(r[1]), "=r"(r[2]), "=r"(r[3]) : "r"(addr));
}
__device__ __forceinline__ void ldsm2(uint32_t* r, uint32_t addr){
    asm volatile("ldmatrix.sync.aligned.m8n8.x2.shared.b16 {%0,%1}, [%2];"
        : "=r"(r[0]), "=r"(r[1]) : "r"(addr));
}
__device__ __forceinline__ void ldsm4t(uint32_t* r, uint32_t addr){
    asm volatile("ldmatrix.sync.aligned.m8n8.x4.trans.shared.b16 {%0,%1,%2,%3}, [%4];"
        : "=r"(r[0]), "=r"(r[1]), "=r"(r[2]), "=r"(r[3]) : "r"(addr));
}
__device__ __forceinline__ void mma_h16(float* d, const uint32_t* a, const uint32_t* b){
    asm volatile("mma.sync.aligned.m16n8k16.row.col.f32.f16.f16.f32 "
        "{%0,%1,%2,%3}, {%4,%5,%6,%7}, {%8,%9}, {%0,%1,%2,%3};"
        : "+f"(d[0]), "+f"(d[1]), "+f"(d[2]), "+f"(d[3])
        : "r"(a[0]), "r"(a[1]), "r"(a[2]), "r"(a[3]), "r"(b[0]), "r"(b[1]));
}
__device__ __forceinline__ uint32_t packh(float hi, float lo){
    uint32_t r;
    asm("cvt.rn.f16x2.f32 %0, %1, %2;" : "=r"(r) : "f"(hi), "f"(lo));
    return r;
}

// Branch-free exp on FMA/ALU pipes only.
__device__ __forceinline__ float fast_exp(float x){
    float xc = fmaxf(x, -87.0f);
    float r  = fmaf(xc, 1.4426950408889634f, 12582912.0f);
    int   n  = __float_as_int(r) - 0x4B400000;
    float fi = r - 12582912.0f;
    float g  = fmaf(fi, -0.6931471805599453f, xc);
    float p  = 8.3333337e-3f;
    p = fmaf(p, g, 4.1666668e-2f);
    p = fmaf(p, g, 1.6666667e-1f);
    p = fmaf(p, g, 0.5f);
    p = fmaf(p, g, 1.0f);
    p = fmaf(p, g, 1.0f);
    return p * __int_as_float((n << 23) + 0x3F800000);
}

#define CP_ASYNC16(sm, gp) \
    asm volatile("cp.async.cg.shared.global [%0], [%1], 16;" :: "r"(sm), "l"(gp))
#define CP_COMMIT() asm volatile("cp.async.commit_group;")
#define CP_WAIT1()  asm volatile("cp.async.wait_group 1;")

// ---------------------------------------------------------------------------
// Fused prep: all fp32 -> fp16 single casts in one launch.
// ---------------------------------------------------------------------------
#define NX4 (MTOT*DIM/4)
#define NW4 (DIM*DIM/4)
#define NPREP (2*NX4 + 4*NW4)

__device__ __forceinline__ void cast_h(
    const float4* __restrict__ x, uint2* __restrict__ h, int i)
{
    float4 v = x[i];
    union { __half b[4]; uint2 u; } H;
    H.b[0] = __float2half_rn(v.x);
    H.b[1] = __float2half_rn(v.y);
    H.b[2] = __float2half_rn(v.z);
    H.b[3] = __float2half_rn(v.w);
    h[i] = H.u;
}

__global__ __launch_bounds__(256) void prep_cast(
    const float4* __restrict__ Xt, const float4* __restrict__ Xf,
    const float4* __restrict__ Wq, const float4* __restrict__ Wk,
    const float4* __restrict__ Wv, const float4* __restrict__ Wo)
{
    int i = blockIdx.x * 256 + threadIdx.x;
    if (i < NX4) {
        cast_h(Xt, (uint2*)g_Xt16, i);
    } else if (i < 2*NX4) {
        cast_h(Xf, (uint2*)g_Xf16, i - NX4);
    } else {
        int j = i - 2*NX4;
        if (j < NW4)           cast_h(Wq, (uint2*)g_Wq16, j);
        else if (j < 2*NW4)    cast_h(Wv, (uint2*)g_Wv16, j - NW4);
        else if (j < 3*NW4)    cast_h(Wk, (uint2*)g_Wk16, j - 2*NW4);
        else if (j < 4*NW4)    cast_h(Wo, (uint2*)g_Wo16, j - 3*NW4);
    }
}

__global__ __launch_bounds__(256) void pack_mask(
    const int* __restrict__ m, uint32_t* __restrict__ bits)
{
    int i = blockIdx.x * 256 + threadIdx.x;
    unsigned v = __ballot_sync(0xffffffffu, m[i] != 0);
    if ((threadIdx.x & 31) == 0) bits[i >> 5] = v;
}

// ---------------------------------------------------------------------------
// fp16 1-term GEMM: C = A·B^T + bias. BK=64 (128B rows, SW128 swizzle).
// 3-stage single-sync, 16 mainloop iterations.
// ---------------------------------------------------------------------------
#define BM 128
#define BN 128
#define BK 64
#define TSZB 16384              // bytes per 128x64 fp16 tile
#define GSTGB (2*TSZB)          // A, B per stage = 32768 bytes
#define GEMM_SMEM (3*GSTGB)     // 98304 bytes

__device__ __forceinline__ void gemm_issue(
    const __half* sA, const __half* sB,
    int kc, uint32_t sstage, int tid)
{
    const __half* src[2] = { sA, sB };
#pragma unroll
    for (int t = 0; t < 2; t++) {
#pragma unroll
        for (int j = 0; j < 4; j++) {
            int idx = tid + j * 256;          // 0..1023
            int r = idx >> 3, c = idx & 7;    // row, 16B chunk (8 per row)
            int cs = c ^ (r & 7);             // SW128
            CP_ASYNC16(sstage + t * TSZB + r * 128 + cs * 16,
                       src[t] + (size_t)r * DIM + kc * BK + c * 8);
        }
    }
}

__global__ __launch_bounds__(256, 2) void gemm_f16(
    const __half* __restrict__ A, const __half* __restrict__ B,
    const float* __restrict__ bias, float* __restrict__ C,
    __half* __restrict__ CH)
{
    extern __shared__ __half smh[];
    const int tid = threadIdx.x, wid = tid >> 5, lane = tid & 31;
    const int bm = blockIdx.y * BM, bn = blockIdx.x * BN;
    const int wm = (wid & 1) * 64, wn = (wid >> 1) * 32;

    const __half* sA = A + (size_t)bm * DIM;
    const __half* sB = B + (size_t)bn * DIM;

    float acc[4][4][4];
#pragma unroll
    for (int i = 0; i < 4; i++)
#pragma unroll
        for (int j = 0; j < 4; j++)
#pragma unroll
            for (int k = 0; k < 4; k++) acc[i][j][k] = 0.0f;

    const int seg = lane >> 3, lr = lane & 7;
    const int a_rowb = (wm + (seg & 1) * 8 + lr) * 128;
    const int b_rowb = (wn + lr) * 128;
    // chunk bases (before ^lr swizzle): A: ks*2 + (seg>>1); B: ks*2 + (seg&1)
    const int aCb = seg >> 1;
    const int bCb = seg & 1;

    const uint32_t sb = smem_u32(smh);

    gemm_issue(sA, sB, 0, sb, tid);          CP_COMMIT();
    gemm_issue(sA, sB, 1, sb + GSTGB, tid);  CP_COMMIT();
    CP_WAIT1();
    __syncthreads();

    for (int kc = 0; kc < DIM / BK; kc++) {   // 16 iterations
        if (kc + 2 < DIM / BK)
            gemm_issue(sA, sB, kc + 2, sb + ((kc + 2) % 3) * GSTGB, tid);
        CP_COMMIT();

        const uint32_t st = sb + (kc % 3) * GSTGB;
#pragma unroll
        for (int ks = 0; ks < 4; ks++) {
            const int cA = ((ks * 2 + aCb) ^ lr) << 4;
            const int cB = ((ks * 2 + bCb) ^ lr) << 4;
            uint32_t bh[4][2];
#pragma unroll
            for (int nt = 0; nt < 4; nt++)
                ldsm2(bh[nt], st + TSZB + b_rowb + nt * (8 * 128) + cB);
#pragma unroll
            for (int mt = 0; mt < 4; mt++) {
                uint32_t ah[4];
                ldsm4(ah, st + a_rowb + mt * (16 * 128) + cA);
#pragma unroll
                for (int nt = 0; nt < 4; nt++)
                    mma_h16(acc[mt][nt], ah, bh[nt]);
            }
        }

        CP_WAIT1();
        __syncthreads();
    }

    const int gr = lane >> 2, gc = (lane & 3) * 2;
#pragma unroll
    for (int mt = 0; mt < 4; mt++) {
#pragma unroll
        for (int nt = 0; nt < 4; nt++) {
            int col  = bn + wn + nt * 8 + gc;
            float b0 = bias[col], b1 = bias[col + 1];
            size_t r0 = (size_t)(bm + wm + mt * 16 + gr) * DIM + col;
            size_t r1 = r0 + 8 * DIM;
            float v0 = acc[mt][nt][0] + b0, v1 = acc[mt][nt][1] + b1;
            float v2 = acc[mt][nt][2] + b0, v3 = acc[mt][nt][3] + b1;
            if (CH) {
                *(uint32_t*)&CH[r0] = packh(v1, v0);
                *(uint32_t*)&CH[r1] = packh(v3, v2);
            } else {
                float2 w0 = { v0, v1 }, w1 = { v2, v3 };
                *(float2*)&C[r0] = w0;
                *(float2*)&C[r1] = w1;
            }
        }
    }
}

// ---------------------------------------------------------------------------
// Tensor-core flash attention (R13-exact math), now 2 CTAs/SM.
// FT=64, 3-stage single-sync KV pipeline.
// ---------------------------------------------------------------------------
#define ALD 72
#define SQ0 0
#define SKV0 9216
#define KVARR 4608
#define KVSTG (2*KVARR)
#define ATT_SMEM ((SKV0 + 3*KVSTG)*2)   // 73728 bytes

__device__ __forceinline__ void kv_issue(
    const __half* K, const __half* V,
    size_t gfrow, int hof, uint32_t stbase, int tid)
{
#pragma unroll
    for (int j = 0; j < 2; j++) {
        int idx = tid + j * 256;
        int r = idx >> 3, c = (idx & 7) * 8;
        size_t g = (gfrow + r) * DIM + hof + c;
        uint32_t so = stbase + (r * ALD + c) * 2;
        CP_ASYNC16(so,             K + g);
        CP_ASYNC16(so + KVARR * 2, V + g);
    }
}

__global__ __launch_bounds__(256, 2) void attn_mma(
    const __half* __restrict__ Q, const __half* __restrict__ K,
    const __half* __restrict__ V,
    const uint32_t* __restrict__ mbits,
    __half* __restrict__ AHo)
{
    extern __shared__ __half sm[];
    const int tid = threadIdx.x, w = tid >> 5, lane = tid & 31;
    const int t0 = blockIdx.x * 128, h = blockIdx.y, b = blockIdx.z;
    const int lr = lane & 7, seg = lane >> 3;
    const int gr = lane >> 2, qc = (lane & 3) * 2;
    const uint32_t sb = smem_u32(sm);
    const int hof = h * HD;
    const size_t gfbase = (size_t)(b * GF);

    kv_issue(K, V, gfbase,      hof, sb + SKV0 * 2, tid);           CP_COMMIT();
    kv_issue(K, V, gfbase + 64, hof, sb + (SKV0 + KVSTG) * 2, tid); CP_COMMIT();

    // Load Q tile
    {
        const size_t grow = (size_t)(b * GT + t0);
#pragma unroll
        for (int j = 0; j < 4; j++) {
            int idx = tid + j * 256;
            int r = idx >> 3, c = (idx & 7) * 8;
            *(uint4*)&sm[SQ0 + r * ALD + c] =
                *(const uint4*)&Q[(grow + r) * DIM + hof + c];
        }
    }
    CP_WAIT1();
    __syncthreads();

    uint32_t qh[4][4];
#pragma unroll
    for (int kc = 0; kc < 4; kc++) {
        uint32_t ad = sb + ((w * 16 + (seg & 1) * 8 + lr) * ALD + kc * 16 + (seg >> 1) * 8) * 2;
        ldsm4(qh[kc], ad + SQ0 * 2);
    }

    float oacc[8][4];
#pragma unroll
    for (int i = 0; i < 8; i++)
#pragma unroll
        for (int j = 0; j < 4; j++) oacc[i][j] = 0.0f;
    float m0 = -1e30f, m1 = -1e30f, l0 = 0.0f, l1 = 0.0f;

    const int mrow0 = b * GT + t0 + w * 16 + gr;
    const uint32_t* mrp0 = mbits + (size_t)mrow0 * (GF / 32);
    const uint32_t* mrp1 = mrp0 + 8 * (GF / 32);

    for (int ftile = 0; ftile < 16; ftile++) {
        if (ftile + 2 < 16)
            kv_issue(K, V, gfbase + (ftile + 2) * 64, hof,
                     sb + (SKV0 + ((ftile + 2) % 3) * KVSTG) * 2, tid);
        CP_COMMIT();

        const uint32_t stg = SKV0 + (ftile % 3) * KVSTG;

        uint2 mw0 = *(const uint2*)(mrp0 + ftile * 2);
        uint2 mw1 = *(const uint2*)(mrp1 + ftile * 2);
        uint32_t wA[2] = { mw0.x, mw0.y };
        uint32_t wB[2] = { mw1.x, mw1.y };

        // S = Q K^T
        float sacc[8][4];
#pragma unroll
        for (int nt = 0; nt < 8; nt++) {
#pragma unroll
            for (int j = 0; j < 4; j++) sacc[nt][j] = 0.0f;
        }
#pragma unroll
        for (int nt = 0; nt < 8; nt++) {
            uint32_t bh[8];
#pragma unroll
            for (int kcg = 0; kcg < 2; kcg++) {
                uint32_t ad = sb + (stg + (nt * 8 + lr) * ALD + kcg * 32 + seg * 8) * 2;
                ldsm4(&bh[kcg * 4], ad);
            }
#pragma unroll
            for (int kc = 0; kc < 4; kc++)
                mma_h16(sacc[nt], qh[kc], &bh[kc * 2]);
        }

        // mask + scale + row max
        float rm0 = -1e30f, rm1 = -1e30f;
#pragma unroll
        for (int nt = 0; nt < 8; nt++) {
            uint32_t sh = (nt & 3) * 8 + qc;
            uint32_t bA = wA[nt >> 2] >> sh;
            uint32_t bB = wB[nt >> 2] >> sh;
            float s0 = (bA & 1u) ? sacc[nt][0] * 0.125f : -10000.0f;
            float s1 = (bA & 2u) ? sacc[nt][1] * 0.125f : -10000.0f;
            float s2 = (bB & 1u) ? sacc[nt][2] * 0.125f : -10000.0f;
            float s3 = (bB & 2u) ? sacc[nt][3] * 0.125f : -10000.0f;
            sacc[nt][0] = s0; sacc[nt][1] = s1; sacc[nt][2] = s2; sacc[nt][3] = s3;
            rm0 = fmaxf(rm0, fmaxf(s0, s1));
            rm1 = fmaxf(rm1, fmaxf(s2, s3));
        }
        rm0 = fmaxf(rm0, __shfl_xor_sync(0xffffffffu, rm0, 1));
        rm0 = fmaxf(rm0, __shfl_xor_sync(0xffffffffu, rm0, 2));
        rm1 = fmaxf(rm1, __shfl_xor_sync(0xffffffffu, rm1, 1));
        rm1 = fmaxf(rm1, __shfl_xor_sync(0xffffffffu, rm1, 2));
        float mn0 = fmaxf(m0, rm0), mn1 = fmaxf(m1, rm1);
        float c0 = fast_exp(m0 - mn0), c1 = fast_exp(m1 - mn1);
        m0 = mn0; m1 = mn1;

        // P = exp(s-m), pack fp16, row sums
        uint32_t pah[4][4];
        float rs0 = 0.0f, rs1 = 0.0f;
#pragma unroll
        for (int kc = 0; kc < 4; kc++) {
            float p0 = fast_exp(sacc[2*kc][0] - m0);
            float p1 = fast_exp(sacc[2*kc][1] - m0);
            float p2 = fast_exp(sacc[2*kc][2] - m1);
            float p3 = fast_exp(sacc[2*kc][3] - m1);
            float p4 = fast_exp(sacc[2*kc+1][0] - m0);
            float p5 = fast_exp(sacc[2*kc+1][1] - m0);
            float p6 = fast_exp(sacc[2*kc+1][2] - m1);
            float p7 = fast_exp(sacc[2*kc+1][3] - m1);
            rs0 += (p0 + p1) + (p4 + p5);
            rs1 += (p2 + p3) + (p6 + p7);
            pah[kc][0] = packh(p1, p0);
            pah[kc][1] = packh(p3, p2);
            pah[kc][2] = packh(p5, p4);
            pah[kc][3] = packh(p7, p6);
        }
        rs0 += __shfl_xor_sync(0xffffffffu, rs0, 1);
        rs0 += __shfl_xor_sync(0xffffffffu, rs0, 2);
        rs1 += __shfl_xor_sync(0xffffffffu, rs1, 1);
        rs1 += __shfl_xor_sync(0xffffffffu, rs1, 2);
        l0 = l0 * c0 + rs0;
        l1 = l1 * c1 + rs1;

#pragma unroll
        for (int nt = 0; nt < 8; nt++) {
            oacc[nt][0] *= c0; oacc[nt][1] *= c0;
            oacc[nt][2] *= c1; oacc[nt][3] *= c1;
        }

        // O += P V
#pragma unroll
        for (int kcg = 0; kcg < 2; kcg++) {
#pragma unroll
            for (int nt = 0; nt < 8; nt++) {
                uint32_t bvh[4];
                uint32_t ad = sb + (stg + KVARR + (kcg * 32 + seg * 8 + lr) * ALD + nt * 8) * 2;
                ldsm4t(bvh, ad);
                mma_h16(oacc[nt], pah[2*kcg],   &bvh[0]);
                mma_h16(oacc[nt], pah[2*kcg+1], &bvh[2]);
            }
        }

        CP_WAIT1();
        __syncthreads();
    }

    // Epilogue: fp16 output
    float inv0 = 1.0f / l0, inv1 = 1.0f / l1;
    size_t orow = (size_t)(b * GT + t0 + w * 16 + gr) * DIM + hof;
#pragma unroll
    for (int nt = 0; nt < 8; nt++) {
        int col = nt * 8 + qc;
        float v0 = oacc[nt][0] * inv0, v1 = oacc[nt][1] * inv0;
        float v2 = oacc[nt][2] * inv1, v3 = oacc[nt][3] * inv1;
        *(uint32_t*)&AHo[orow + col] = packh(v1, v0);
        *(uint32_t*)&AHo[orow + 8 * DIM + col] = packh(v3, v2);
    }
}

// ---------------------------------------------------------------------------
// Launch
// ---------------------------------------------------------------------------
extern "C" void kernel_launch(void* const* d_in, const int* in_sizes, int n_in,
                              void* d_out, int out_size)
{
    const float* X_to   = (const float*)d_in[0];
    const float* X_from = (const float*)d_in[1];
    const int*   maskp  = (const int*)  d_in[2];
    const float* Wq = (const float*)d_in[3];
    const float* bq = (const float*)d_in[4];
    const float* Wk = (const float*)d_in[5];
    const float* bk = (const float*)d_in[6];
    const float* Wv = (const float*)d_in[7];
    const float* bv = (const float*)d_in[8];
    const float* Wo = (const float*)d_in[9];
    const float* bo = (const float*)d_in[10];
    float* out = (float*)d_out;

    __half *Q,*K,*V,*A,*Xt16,*Xf16,*Wq16,*Wk16,*Wv16,*Wo16;
    uint32_t* mbits;
    cudaGetSymbolAddress((void**)&Q, g_Q);
    cudaGetSymbolAddress((void**)&K, g_K);
    cudaGetSymbolAddress((void**)&V, g_V);
    cudaGetSymbolAddress((void**)&A, g_A);
    cudaGetSymbolAddress((void**)&Xt16, g_Xt16);
    cudaGetSymbolAddress((void**)&Xf16, g_Xf16);
    cudaGetSymbolAddress((void**)&Wq16, g_Wq16);
    cudaGetSymbolAddress((void**)&Wk16, g_Wk16);
    cudaGetSymbolAddress((void**)&Wv16, g_Wv16);
    cudaGetSymbolAddress((void**)&Wo16, g_Wo16);
    cudaGetSymbolAddress((void**)&mbits, g_mbits);

    cudaFuncSetAttribute(gemm_f16,
                         cudaFuncAttributeMaxDynamicSharedMemorySize, GEMM_SMEM);
    cudaFuncSetAttribute(attn_mma,
                         cudaFuncAttributeMaxDynamicSharedMemorySize, ATT_SMEM);

    prep_cast<<<NPREP / 256, 256>>>((const float4*)X_to, (const float4*)X_from,
                                    (const float4*)Wq, (const float4*)Wk,
                                    (const float4*)Wv, (const float4*)Wo);
    pack_mask<<<(MTOT * GF) / 256, 256>>>(maskp, mbits);

    dim3 gg(DIM / BN, MTOT / BM);   // (8, 32)

    // Projections (fp16 1-term). NOTE reference's swap: K <= Wv/bv, V <= Wk/bk.
    gemm_f16<<<gg, 256, GEMM_SMEM>>>(Xt16, Wq16, bq, nullptr, Q);
    gemm_f16<<<gg, 256, GEMM_SMEM>>>(Xf16, Wv16, bv, nullptr, K);
    gemm_f16<<<gg, 256, GEMM_SMEM>>>(Xf16, Wk16, bk, nullptr, V);

    dim3 ag(GT / 128, GH, GB);      // (8, 16, 4)
    attn_mma<<<ag, 256, ATT_SMEM>>>(Q, K, V, mbits, A);

    // Output projection (fp16 1-term, fp32 out)
    gemm_f16<<<gg, 256, GEMM_SMEM>>>(A, Wo16, bo, out, nullptr);
}